// round 8
// baseline (speedup 1.0000x reference)
#include <cuda_runtime.h>
#include <cstdint>

#define DMODEL 1024
#define NHEADS 16
#define DK     64
#define BATCH  2
#define SEQ    2048
#define MTOT   (BATCH * SEQ)   // 4096

// Scratch (static __device__ — allocation-free per harness rules)
__device__ float g_Q[(size_t)BATCH * NHEADS * SEQ * DK];
__device__ float g_K[(size_t)BATCH * NHEADS * SEQ * DK];
__device__ float g_V[(size_t)BATCH * NHEADS * SEQ * DK];
__device__ float g_ctx[(size_t)BATCH * SEQ * DMODEL];

// ===========================================================================
// Warp-level MMA plumbing (sm_80+ PTX — valid on compute_103, runs as HMMA)
// ===========================================================================
__device__ __forceinline__ uint32_t smem_u32(const void* p) {
    uint32_t a;
    asm("{ .reg .u64 t; cvta.to.shared.u64 t, %1; cvt.u32.u64 %0, t; }"
        : "=r"(a) : "l"(p));
    return a;
}

__device__ __forceinline__ void ldsm_x4(uint32_t addr, uint32_t& r0, uint32_t& r1,
                                        uint32_t& r2, uint32_t& r3) {
    asm volatile("ldmatrix.sync.aligned.m8n8.x4.shared.b16 {%0,%1,%2,%3}, [%4];"
                 : "=r"(r0), "=r"(r1), "=r"(r2), "=r"(r3) : "r"(addr));
}

__device__ __forceinline__ void ldsm_x2(uint32_t addr, uint32_t& r0, uint32_t& r1) {
    asm volatile("ldmatrix.sync.aligned.m8n8.x2.shared.b16 {%0,%1}, [%2];"
                 : "=r"(r0), "=r"(r1) : "r"(addr));
}

__device__ __forceinline__ void mma16816(float* d, const uint32_t* a,
                                         const uint32_t* b) {
    asm volatile(
        "mma.sync.aligned.m16n8k16.row.col.f32.bf16.bf16.f32 "
        "{%0,%1,%2,%3}, {%4,%5,%6,%7}, {%8,%9}, {%0,%1,%2,%3};"
        : "+f"(d[0]), "+f"(d[1]), "+f"(d[2]), "+f"(d[3])
        : "r"(a[0]), "r"(a[1]), "r"(a[2]), "r"(a[3]), "r"(b[0]), "r"(b[1]));
}

// Split float4 -> packed bf16 hi pair + lo pair (truncation; hi+lo ~ 2^-17 rel)
__device__ __forceinline__ void split4(float4 v, uint32_t& h0, uint32_t& h1,
                                       uint32_t& l0, uint32_t& l1) {
    uint32_t xi = __float_as_uint(v.x), yi = __float_as_uint(v.y);
    uint32_t zi = __float_as_uint(v.z), wi = __float_as_uint(v.w);
    asm("prmt.b32 %0, %1, %2, 0x7632;" : "=r"(h0) : "r"(xi), "r"(yi));
    asm("prmt.b32 %0, %1, %2, 0x7632;" : "=r"(h1) : "r"(zi), "r"(wi));
    float lx = v.x - __uint_as_float(xi & 0xffff0000u);
    float ly = v.y - __uint_as_float(yi & 0xffff0000u);
    float lz = v.z - __uint_as_float(zi & 0xffff0000u);
    float lw = v.w - __uint_as_float(wi & 0xffff0000u);
    asm("prmt.b32 %0, %1, %2, 0x7632;"
        : "=r"(l0) : "r"(__float_as_uint(lx)), "r"(__float_as_uint(ly)));
    asm("prmt.b32 %0, %1, %2, 0x7632;"
        : "=r"(l1) : "r"(__float_as_uint(lz)), "r"(__float_as_uint(lw)));
}

#define BM    128
#define BN    64
#define PITCH 104         // bf16 elements per smem row (96 data + 8 pad)

// ---------------------------------------------------------------------------
// Shared HMMA mainloop: acc[2][4][4] += A[128 x 1024] · B[64 x 1024]^T
// 3-term bf16 split, concatenated-K layout per 32-col fp32 slab:
//   A' cols 0-31 = Ahi, 32-63 = Alo, 64-95 = Ahi   (duplicated)
//   B' cols 0-31 = Bhi, 32-63 = Bhi, 64-95 = Blo
// => inner product = Ahi·Bhi + Alo·Bhi + Ahi·Blo (lo·lo dropped, ~2^-18).
// 8 warps: 4 m-groups x 2 n-groups of 32x32.
// ---------------------------------------------------------------------------
__device__ __forceinline__ void mma_mainloop(const float* __restrict__ Ab,
                                             const float* __restrict__ Bb,
                                             uint16_t* AsmP, uint16_t* BsmP,
                                             float acc[2][4][4])
{
    const int tid  = threadIdx.x;
    const int lane = tid & 31;
    const int wid  = tid >> 5;
    const int mw   = (wid & 3) * 32;
    const int nw   = (wid >> 2) * 32;

    const uint32_t sA = smem_u32(AsmP);
    const uint32_t sB = smem_u32(BsmP);

    const int lrow = tid >> 3;          // 0..31 base row for loads
    const int lc   = tid & 7;           // float4 column (0..7)

    const float* ap = Ab + (size_t)lrow * DMODEL + lc * 4;
    const float* bp = Bb + (size_t)lrow * DMODEL + lc * 4;   // rows 0..63 via j<2

    // smem store byte offset of hi segment (col lc*4)
    const uint32_t aoff = (uint32_t)(lrow * PITCH + lc * 4) * 2;

    float4 pa[4], pb[2];
#pragma unroll
    for (int j = 0; j < 4; j++) pa[j] = *(const float4*)(ap + (size_t)(32 * j) * DMODEL);
#pragma unroll
    for (int j = 0; j < 2; j++) pb[j] = *(const float4*)(bp + (size_t)(32 * j) * DMODEL);

    // ldmatrix fragment base addresses (byte)
    const uint32_t afrag = sA + (uint32_t)((mw + (lane & 15)) * PITCH + (lane >> 4) * 8) * 2;
    const uint32_t bfrag = sB + (uint32_t)((nw + (lane & 7)) * PITCH + ((lane >> 3) & 1) * 8) * 2;

    for (int it = 0; it < 32; ++it) {
        __syncthreads();
#pragma unroll
        for (int j = 0; j < 4; j++) {
            uint32_t h0, h1, l0, l1;
            split4(pa[j], h0, h1, l0, l1);
            const uint32_t o = sA + aoff + (uint32_t)(32 * j * PITCH) * 2;
            asm volatile("st.shared.v2.b32 [%0], {%1, %2};" :: "r"(o),       "r"(h0), "r"(h1));
            asm volatile("st.shared.v2.b32 [%0], {%1, %2};" :: "r"(o + 64),  "r"(l0), "r"(l1));
            asm volatile("st.shared.v2.b32 [%0], {%1, %2};" :: "r"(o + 128), "r"(h0), "r"(h1));
        }
#pragma unroll
        for (int j = 0; j < 2; j++) {
            uint32_t h0, h1, l0, l1;
            split4(pb[j], h0, h1, l0, l1);
            const uint32_t o = sB + aoff + (uint32_t)(32 * j * PITCH) * 2;
            asm volatile("st.shared.v2.b32 [%0], {%1, %2};" :: "r"(o),       "r"(h0), "r"(h1));
            asm volatile("st.shared.v2.b32 [%0], {%1, %2};" :: "r"(o + 64),  "r"(h0), "r"(h1));
            asm volatile("st.shared.v2.b32 [%0], {%1, %2};" :: "r"(o + 128), "r"(l0), "r"(l1));
        }
        __syncthreads();

        if (it + 1 < 32) {               // prefetch next fp32 slab
            const int k0 = (it + 1) * 32;
#pragma unroll
            for (int j = 0; j < 4; j++)
                pa[j] = *(const float4*)(ap + k0 + (size_t)(32 * j) * DMODEL);
#pragma unroll
            for (int j = 0; j < 2; j++)
                pb[j] = *(const float4*)(bp + k0 + (size_t)(32 * j) * DMODEL);
        }

#pragma unroll
        for (int ks = 0; ks < 6; ks++) {            // 6 x K=16 over 96 bf16 cols
            uint32_t a[2][4], b[4][2];
#pragma unroll
            for (int mt = 0; mt < 2; mt++)
                ldsm_x4(afrag + (uint32_t)(mt * 16 * PITCH + ks * 16) * 2,
                        a[mt][0], a[mt][1], a[mt][2], a[mt][3]);
#pragma unroll
            for (int nt = 0; nt < 4; nt++)
                ldsm_x2(bfrag + (uint32_t)(nt * 8 * PITCH + ks * 16) * 2,
                        b[nt][0], b[nt][1]);
#pragma unroll
            for (int mt = 0; mt < 2; mt++)
#pragma unroll
                for (int nt = 0; nt < 4; nt++)
                    mma16816(acc[mt][nt], a[mt], b[nt]);
        }
    }
}

// ---------------------------------------------------------------------------
// QKV projection (HMMA): C[m,n] = x·W^T + bias, scattered to [b,h,s,dk].
// Logical N = 3072 (Q|K|V); BN=64 aligns with head and matrix boundaries.
// ---------------------------------------------------------------------------
__global__ __launch_bounds__(256, 2)
void qkv_mma_kernel(const float* __restrict__ x,
                    const float* __restrict__ Wq, const float* __restrict__ bq,
                    const float* __restrict__ Wk, const float* __restrict__ bk,
                    const float* __restrict__ Wv, const float* __restrict__ bv)
{
    __shared__ __align__(16) uint16_t Asm[BM * PITCH];
    __shared__ __align__(16) uint16_t Bsm[BN * PITCH];

    const int m0   = blockIdx.x * BM;
    const int n0g  = blockIdx.y * BN;
    const int wsel = n0g >> 10;
    const int n0   = n0g & 1023;

    const float* __restrict__ W   = (wsel == 0) ? Wq : ((wsel == 1) ? Wk : Wv);
    const float* __restrict__ bia = (wsel == 0) ? bq : ((wsel == 1) ? bk : bv);
    float* __restrict__ dst       = (wsel == 0) ? g_Q : ((wsel == 1) ? g_K : g_V);

    float acc[2][4][4];
#pragma unroll
    for (int i = 0; i < 2; i++)
#pragma unroll
        for (int j = 0; j < 4; j++)
#pragma unroll
            for (int k = 0; k < 4; k++) acc[i][j][k] = 0.f;

    mma_mainloop(x + (size_t)m0 * DMODEL, W + (size_t)n0 * DMODEL, Asm, Bsm, acc);

    const int lane = threadIdx.x & 31;
    const int wid  = threadIdx.x >> 5;
    const int mw   = (wid & 3) * 32;
    const int nw   = (wid >> 2) * 32;

#pragma unroll
    for (int mt = 0; mt < 2; mt++) {
#pragma unroll
        for (int nt = 0; nt < 4; nt++) {
            const int n    = n0 + nw + nt * 8 + (lane & 3) * 2;
            const int head = n >> 6;
            const int dk   = n & 63;
            const float b0v = __ldg(bia + n), b1v = __ldg(bia + n + 1);
#pragma unroll
            for (int hh = 0; hh < 2; hh++) {
                const int m    = m0 + mw + mt * 16 + (lane >> 2) + hh * 8;
                const int bb   = m >> 11;
                const int srow = m & (SEQ - 1);
                float2 v = make_float2(acc[mt][nt][hh * 2] + b0v,
                                       acc[mt][nt][hh * 2 + 1] + b1v);
                *(float2*)(dst + ((size_t)((bb * NHEADS + head) * SEQ + srow)) * DK + dk) = v;
            }
        }
    }
}

// ---------------------------------------------------------------------------
// Output projection (HMMA): out = ctx·Wo^T + bo
// ---------------------------------------------------------------------------
__global__ __launch_bounds__(256, 2)
void oproj_mma_kernel(const float* __restrict__ Wo,
                      const float* __restrict__ bo,
                      float* __restrict__ out)
{
    __shared__ __align__(16) uint16_t Asm[BM * PITCH];
    __shared__ __align__(16) uint16_t Bsm[BN * PITCH];

    const int m0 = blockIdx.x * BM;
    const int n0 = blockIdx.y * BN;

    float acc[2][4][4];
#pragma unroll
    for (int i = 0; i < 2; i++)
#pragma unroll
        for (int j = 0; j < 4; j++)
#pragma unroll
            for (int k = 0; k < 4; k++) acc[i][j][k] = 0.f;

    mma_mainloop(g_ctx + (size_t)m0 * DMODEL, Wo + (size_t)n0 * DMODEL, Asm, Bsm, acc);

    const int lane = threadIdx.x & 31;
    const int wid  = threadIdx.x >> 5;
    const int mw   = (wid & 3) * 32;
    const int nw   = (wid >> 2) * 32;

#pragma unroll
    for (int mt = 0; mt < 2; mt++) {
#pragma unroll
        for (int nt = 0; nt < 4; nt++) {
            const int n = n0 + nw + nt * 8 + (lane & 3) * 2;
            const float b0v = __ldg(bo + n), b1v = __ldg(bo + n + 1);
#pragma unroll
            for (int hh = 0; hh < 2; hh++) {
                const int m = m0 + mw + mt * 16 + (lane >> 2) + hh * 8;
                float2 v = make_float2(acc[mt][nt][hh * 2] + b0v,
                                       acc[mt][nt][hh * 2 + 1] + b1v);
                *(float2*)(out + (size_t)m * DMODEL + n) = v;
            }
        }
    }
}

// ---------------------------------------------------------------------------
// Causal flash attention, fp32 (proven in R3; HMMA port next round).
// ---------------------------------------------------------------------------
#define ASTR 65

__global__ __launch_bounds__(256)
void attn_kernel()
{
    extern __shared__ float sm[];
    float* Qs = sm;
    float* Ks = Qs + 64 * ASTR;
    float* Vs = Ks + 64 * ASTR;
    float* Ps = Vs + 64 * ASTR;

    const int bid = blockIdx.x;
    const int qb  = bid & 31;
    const int h   = (bid >> 5) & (NHEADS - 1);
    const int b   = bid >> 9;

    const int tid = threadIdx.x;
    const int tx  = tid & 15;
    const int ty  = tid >> 4;

    const size_t headbase = (size_t)(b * NHEADS + h) * SEQ * DK;
    const float* Qbase = g_Q + headbase + (size_t)qb * 64 * DK;
    const float* Kh    = g_K + headbase;
    const float* Vh    = g_V + headbase;

    for (int idx = tid; idx < 64 * 64; idx += 256) {
        const int r = idx >> 6, d = idx & 63;
        Qs[r * ASTR + d] = Qbase[r * DK + d];
    }

    float o[4][4];
    float mrow[4], lrow[4];
#pragma unroll
    for (int i = 0; i < 4; i++) {
        mrow[i] = -1e30f;
        lrow[i] = 0.f;
#pragma unroll
        for (int j = 0; j < 4; j++) o[i][j] = 0.f;
    }

    for (int jt = 0; jt <= qb; jt++) {
        __syncthreads();

        const float* Kb = Kh + (size_t)jt * 64 * DK;
        const float* Vb = Vh + (size_t)jt * 64 * DK;
        for (int idx = tid; idx < 64 * 64; idx += 256) {
            const int r = idx >> 6, d = idx & 63;
            Ks[r * ASTR + d] = Kb[r * DK + d];
            Vs[r * ASTR + d] = Vb[r * DK + d];
        }
        __syncthreads();

        float s[4][4];
#pragma unroll
        for (int i = 0; i < 4; i++)
#pragma unroll
            for (int j = 0; j < 4; j++) s[i][j] = 0.f;

#pragma unroll 16
        for (int d = 0; d < 64; d++) {
            float qv[4], kv[4];
#pragma unroll
            for (int i = 0; i < 4; i++) qv[i] = Qs[(ty * 4 + i) * ASTR + d];
#pragma unroll
            for (int j = 0; j < 4; j++) kv[j] = Ks[(tx * 4 + j) * ASTR + d];
#pragma unroll
            for (int i = 0; i < 4; i++)
#pragma unroll
                for (int j = 0; j < 4; j++)
                    s[i][j] += qv[i] * kv[j];
        }

        const float scale = 0.125f;
        if (jt == qb) {
#pragma unroll
            for (int i = 0; i < 4; i++) {
                const int qg = (qb << 6) + (ty << 2) + i;
#pragma unroll
                for (int j = 0; j < 4; j++) {
                    const int kg = (jt << 6) + (tx << 2) + j;
                    s[i][j] = (kg <= qg) ? s[i][j] * scale : -1e30f;
                }
            }
        } else {
#pragma unroll
            for (int i = 0; i < 4; i++)
#pragma unroll
                for (int j = 0; j < 4; j++) s[i][j] *= scale;
        }

        float mnew[4], alpha[4];
#pragma unroll
        for (int i = 0; i < 4; i++) {
            float v = fmaxf(fmaxf(s[i][0], s[i][1]), fmaxf(s[i][2], s[i][3]));
#pragma unroll
            for (int off = 8; off > 0; off >>= 1)
                v = fmaxf(v, __shfl_xor_sync(0xffffffffu, v, off));
            mnew[i]  = fmaxf(mrow[i], v);
            alpha[i] = __expf(mrow[i] - mnew[i]);
        }
#pragma unroll
        for (int i = 0; i < 4; i++) {
            float rs = 0.f;
#pragma unroll
            for (int j = 0; j < 4; j++) {
                const float p = __expf(s[i][j] - mnew[i]);
                s[i][j] = p;
                rs += p;
            }
#pragma unroll
            for (int off = 8; off > 0; off >>= 1)
                rs += __shfl_xor_sync(0xffffffffu, rs, off);
            lrow[i] = lrow[i] * alpha[i] + rs;
            mrow[i] = mnew[i];
#pragma unroll
            for (int j = 0; j < 4; j++) o[i][j] *= alpha[i];
        }

#pragma unroll
        for (int i = 0; i < 4; i++)
#pragma unroll
            for (int j = 0; j < 4; j++)
                Ps[(ty * 4 + i) * ASTR + tx * 4 + j] = s[i][j];
        __syncthreads();

#pragma unroll 16
        for (int kk = 0; kk < 64; kk++) {
            float pv[4], vv[4];
#pragma unroll
            for (int i = 0; i < 4; i++) pv[i] = Ps[(ty * 4 + i) * ASTR + kk];
#pragma unroll
            for (int j = 0; j < 4; j++) vv[j] = Vs[kk * ASTR + tx * 4 + j];
#pragma unroll
            for (int i = 0; i < 4; i++)
#pragma unroll
                for (int j = 0; j < 4; j++)
                    o[i][j] += pv[i] * vv[j];
        }
    }

#pragma unroll
    for (int i = 0; i < 4; i++) {
        const int r = (qb << 6) + (ty << 2) + i;
        const float inv = 1.f / lrow[i];
#pragma unroll
        for (int j = 0; j < 4; j++) {
            g_ctx[((size_t)(b * SEQ + r)) * DMODEL + h * DK + tx * 4 + j] =
                o[i][j] * inv;
        }
    }
}

// ---------------------------------------------------------------------------
extern "C" void kernel_launch(void* const* d_in, const int* in_sizes, int n_in,
                              void* d_out, int out_size)
{
    const float* x  = (const float*)d_in[0];
    // d_in[1] = mask (causal; statically known, unused)
    const float* Wq = (const float*)d_in[2];
    const float* bq = (const float*)d_in[3];
    const float* Wk = (const float*)d_in[4];
    const float* bk = (const float*)d_in[5];
    const float* Wv = (const float*)d_in[6];
    const float* bv = (const float*)d_in[7];
    const float* Wo = (const float*)d_in[8];
    const float* bo = (const float*)d_in[9];
    float* out = (float*)d_out;

    const int attn_smem = 4 * 64 * ASTR * (int)sizeof(float);   // 66560 B
    cudaFuncSetAttribute(attn_kernel,
                         cudaFuncAttributeMaxDynamicSharedMemorySize, attn_smem);

    qkv_mma_kernel<<<dim3(MTOT / BM, 3 * DMODEL / BN), 256>>>(
        x, Wq, bq, Wk, bk, Wv, bv);
    attn_kernel<<<BATCH * NHEADS * (SEQ / 64), 256, attn_smem>>>();
    oproj_mma_kernel<<<dim3(MTOT / BM, DMODEL / BN), 256>>>(Wo, bo, out);
}

// round 11
// speedup vs baseline: 1.5573x; 1.5573x over previous
#include <cuda_runtime.h>
#include <cstdint>

#define DMODEL 1024
#define NHEADS 16
#define DK     64
#define BATCH  2
#define SEQ    2048
#define MTOT   (BATCH * SEQ)   // 4096

// Scratch (static __device__ — allocation-free per harness rules)
__device__ float g_Q[(size_t)BATCH * NHEADS * SEQ * DK];
__device__ float g_K[(size_t)BATCH * NHEADS * SEQ * DK];
__device__ float g_V[(size_t)BATCH * NHEADS * SEQ * DK];
__device__ float g_ctx[(size_t)BATCH * SEQ * DMODEL];

// bf16 hi/lo split arrays (truncation split, proven rel_err 4.5e-5)
__device__ uint16_t g_xhi[(size_t)MTOT * DMODEL];
__device__ uint16_t g_xlo[(size_t)MTOT * DMODEL];
__device__ uint16_t g_whi[(size_t)4096 * DMODEL];   // rows: Wq|Wk|Wv|Wo
__device__ uint16_t g_wlo[(size_t)4096 * DMODEL];
__device__ uint16_t g_chi[(size_t)MTOT * DMODEL];
__device__ uint16_t g_clo[(size_t)MTOT * DMODEL];

// ===========================================================================
// Warp-level MMA plumbing (sm_80+ PTX — valid on compute_103, runs as HMMA)
// ===========================================================================
__device__ __forceinline__ uint32_t smem_u32(const void* p) {
    uint32_t a;
    asm("{ .reg .u64 t; cvta.to.shared.u64 t, %1; cvt.u32.u64 %0, t; }"
        : "=r"(a) : "l"(p));
    return a;
}

__device__ __forceinline__ void ldsm_x4(uint32_t addr, uint32_t& r0, uint32_t& r1,
                                        uint32_t& r2, uint32_t& r3) {
    asm volatile("ldmatrix.sync.aligned.m8n8.x4.shared.b16 {%0,%1,%2,%3}, [%4];"
                 : "=r"(r0), "=r"(r1), "=r"(r2), "=r"(r3) : "r"(addr));
}

__device__ __forceinline__ void ldsm_x2(uint32_t addr, uint32_t& r0, uint32_t& r1) {
    asm volatile("ldmatrix.sync.aligned.m8n8.x2.shared.b16 {%0,%1}, [%2];"
                 : "=r"(r0), "=r"(r1) : "r"(addr));
}

__device__ __forceinline__ void mma16816(float* d, const uint32_t* a,
                                         const uint32_t* b) {
    asm volatile(
        "mma.sync.aligned.m16n8k16.row.col.f32.bf16.bf16.f32 "
        "{%0,%1,%2,%3}, {%4,%5,%6,%7}, {%8,%9}, {%0,%1,%2,%3};"
        : "+f"(d[0]), "+f"(d[1]), "+f"(d[2]), "+f"(d[3])
        : "r"(a[0]), "r"(a[1]), "r"(a[2]), "r"(a[3]), "r"(b[0]), "r"(b[1]));
}

__device__ __forceinline__ void cpa16(uint32_t dst, const void* src) {
    asm volatile("cp.async.cg.shared.global [%0], [%1], 16;"
                 :: "r"(dst), "l"(src));
}
#define CP_COMMIT()  asm volatile("cp.async.commit_group;" ::: "memory")
#define CP_WAIT(N)   asm volatile("cp.async.wait_group %0;" :: "n"(N) : "memory")

// Split float4 -> packed bf16 hi pair + lo pair (truncation; 3-term ~2^-17)
__device__ __forceinline__ void split4(float4 v, uint32_t& h0, uint32_t& h1,
                                       uint32_t& l0, uint32_t& l1) {
    uint32_t xi = __float_as_uint(v.x), yi = __float_as_uint(v.y);
    uint32_t zi = __float_as_uint(v.z), wi = __float_as_uint(v.w);
    asm("prmt.b32 %0, %1, %2, 0x7632;" : "=r"(h0) : "r"(xi), "r"(yi));
    asm("prmt.b32 %0, %1, %2, 0x7632;" : "=r"(h1) : "r"(zi), "r"(wi));
    float lx = v.x - __uint_as_float(xi & 0xffff0000u);
    float ly = v.y - __uint_as_float(yi & 0xffff0000u);
    float lz = v.z - __uint_as_float(zi & 0xffff0000u);
    float lw = v.w - __uint_as_float(wi & 0xffff0000u);
    asm("prmt.b32 %0, %1, %2, 0x7632;"
        : "=r"(l0) : "r"(__float_as_uint(lx)), "r"(__float_as_uint(ly)));
    asm("prmt.b32 %0, %1, %2, 0x7632;"
        : "=r"(l1) : "r"(__float_as_uint(lz)), "r"(__float_as_uint(lw)));
}

// ===========================================================================
// Split precompute kernels (gmem fp32 -> bf16 hi/lo)
// ===========================================================================
__global__ __launch_bounds__(256)
void split_x_kernel(const float* __restrict__ x)
{
    const size_t e = ((size_t)blockIdx.x * 256 + threadIdx.x) * 4;
    float4 v = *(const float4*)(x + e);
    uint32_t h0, h1, l0, l1;
    split4(v, h0, h1, l0, l1);
    *(uint2*)(g_xhi + e) = make_uint2(h0, h1);
    *(uint2*)(g_xlo + e) = make_uint2(l0, l1);
}

__global__ __launch_bounds__(256)
void split_w_kernel(const float* __restrict__ Wq, const float* __restrict__ Wk,
                    const float* __restrict__ Wv, const float* __restrict__ Wo)
{
    const int wsel = blockIdx.y;
    const float* src = (wsel == 0) ? Wq : (wsel == 1) ? Wk : (wsel == 2) ? Wv : Wo;
    const size_t e = ((size_t)blockIdx.x * 256 + threadIdx.x) * 4;
    float4 v = *(const float4*)(src + e);
    uint32_t h0, h1, l0, l1;
    split4(v, h0, h1, l0, l1);
    const size_t d = (size_t)wsel * DMODEL * DMODEL + e;
    *(uint2*)(g_whi + d) = make_uint2(h0, h1);
    *(uint2*)(g_wlo + d) = make_uint2(l0, l1);
}

__global__ __launch_bounds__(256)
void split_ctx_kernel()
{
    const size_t e = ((size_t)blockIdx.x * 256 + threadIdx.x) * 4;
    float4 v = *(const float4*)(g_ctx + e);
    uint32_t h0, h1, l0, l1;
    split4(v, h0, h1, l0, l1);
    *(uint2*)(g_chi + e) = make_uint2(h0, h1);
    *(uint2*)(g_clo + e) = make_uint2(l0, l1);
}

// ===========================================================================
// HMMA GEMM: C[128 x 64] = A[128,1024] · B[64,1024]^T, 3-term bf16 split.
// Smem row (144 B): bytes 0-63 = 32 hi cols, 64-127 = 32 lo cols, 16 pad.
// Double-buffered cp.async; register-reuse: t0=Ahi·Bhi, t1=Ahi·Blo, t2=Alo·Bhi.
// 8 warps as 4(m) x 2(n); warp tile 32x32 (mt<2 of 16, nt<4 of 8).
// ===========================================================================
#define BM      128
#define BN      64
#define ROWPB   144                 // bytes per row
#define ABYTES  (BM * ROWPB)        // 18432
#define BUFB    ((BM + BN) * ROWPB) // 27648
#define SMEM_G  (2 * BUFB)          // 55296

__device__ __forceinline__ void gemm_loadslab(uint32_t sb, int buf, int k0,
                                              const uint16_t* __restrict__ Ahi,
                                              const uint16_t* __restrict__ Alo,
                                              const uint16_t* __restrict__ Bhi,
                                              const uint16_t* __restrict__ Blo)
{
    const int tid = threadIdx.x;
    const uint32_t base = sb + buf * BUFB;
    if (tid < 128) {
        // one A row per thread: 64B hi + 64B lo = 8 x 16B chunks
        const int r = tid;
        const uint16_t* hs = Ahi + (size_t)r * DMODEL + k0;
        const uint16_t* ls = Alo + (size_t)r * DMODEL + k0;
        const uint32_t d = base + r * ROWPB;
#pragma unroll
        for (int c = 0; c < 4; c++) {
            cpa16(d + c * 16,      hs + c * 8);
            cpa16(d + 64 + c * 16, ls + c * 8);
        }
    } else {
        // two threads per B row; thread h covers 32B of hi + 32B of lo
        const int t = tid - 128;
        const int r = t >> 1, h = t & 1;
        const uint16_t* hs = Bhi + (size_t)r * DMODEL + k0 + h * 16;
        const uint16_t* ls = Blo + (size_t)r * DMODEL + k0 + h * 16;
        const uint32_t d = base + ABYTES + r * ROWPB + h * 32;
#pragma unroll
        for (int c = 0; c < 2; c++) {
            cpa16(d + c * 16,      hs + c * 8);
            cpa16(d + 64 + c * 16, ls + c * 8);
        }
    }
    CP_COMMIT();
}

__device__ __forceinline__ void gemm_mainloop(uint32_t sb,
                                              const uint16_t* __restrict__ Ahi,
                                              const uint16_t* __restrict__ Alo,
                                              const uint16_t* __restrict__ Bhi,
                                              const uint16_t* __restrict__ Blo,
                                              float acc[2][4][4])
{
    const int tid  = threadIdx.x;
    const int lane = tid & 31;
    const int wid  = tid >> 5;
    const int mw   = (wid & 3) * 32;
    const int nw   = (wid >> 2) * 32;

    // per-thread ldmatrix base offsets (bytes, within buffer)
    const uint32_t aoff = (uint32_t)((mw + (lane & 15)) * ROWPB + (lane >> 4) * 16);
    const uint32_t boff = (uint32_t)((nw + (lane & 7)) * ROWPB + ((lane >> 3) & 1) * 16);

    gemm_loadslab(sb, 0, 0, Ahi, Alo, Bhi, Blo);
    gemm_loadslab(sb, 1, 32, Ahi, Alo, Bhi, Blo);

#pragma unroll 1
    for (int it = 0; it < 32; ++it) {
        if (it == 31) { CP_WAIT(0); } else { CP_WAIT(1); }
        __syncthreads();

        const uint32_t bA = sb + (it & 1) * BUFB;
        const uint32_t bB = bA + ABYTES;

        uint32_t ahi[2][2][4], bhi[2][4][2], blo[2][4][2];
        // A-hi frags (hi bytes 0-63: unit u at byte u*32)
#pragma unroll
        for (int u = 0; u < 2; u++)
#pragma unroll
            for (int mt = 0; mt < 2; mt++)
                ldsm_x4(bA + aoff + (uint32_t)(mt * 16 * ROWPB + u * 32),
                        ahi[u][mt][0], ahi[u][mt][1], ahi[u][mt][2], ahi[u][mt][3]);
        // B-hi frags
#pragma unroll
        for (int u = 0; u < 2; u++)
#pragma unroll
            for (int nt = 0; nt < 4; nt++)
                ldsm_x2(bB + boff + (uint32_t)(nt * 8 * ROWPB + u * 32),
                        bhi[u][nt][0], bhi[u][nt][1]);
        // t0: Ahi·Bhi
#pragma unroll
        for (int u = 0; u < 2; u++)
#pragma unroll
            for (int mt = 0; mt < 2; mt++)
#pragma unroll
                for (int nt = 0; nt < 4; nt++)
                    mma16816(acc[mt][nt], ahi[u][mt], bhi[u][nt]);
        // B-lo frags (lo bytes 64-127)
#pragma unroll
        for (int u = 0; u < 2; u++)
#pragma unroll
            for (int nt = 0; nt < 4; nt++)
                ldsm_x2(bB + boff + (uint32_t)(nt * 8 * ROWPB + u * 32 + 64),
                        blo[u][nt][0], blo[u][nt][1]);
        // t1: Ahi·Blo
#pragma unroll
        for (int u = 0; u < 2; u++)
#pragma unroll
            for (int mt = 0; mt < 2; mt++)
#pragma unroll
                for (int nt = 0; nt < 4; nt++)
                    mma16816(acc[mt][nt], ahi[u][mt], blo[u][nt]);
        // A-lo frags overwrite A-hi registers
#pragma unroll
        for (int u = 0; u < 2; u++)
#pragma unroll
            for (int mt = 0; mt < 2; mt++)
                ldsm_x4(bA + aoff + (uint32_t)(mt * 16 * ROWPB + u * 32 + 64),
                        ahi[u][mt][0], ahi[u][mt][1], ahi[u][mt][2], ahi[u][mt][3]);
        // t2: Alo·Bhi
#pragma unroll
        for (int u = 0; u < 2; u++)
#pragma unroll
            for (int mt = 0; mt < 2; mt++)
#pragma unroll
                for (int nt = 0; nt < 4; nt++)
                    mma16816(acc[mt][nt], ahi[u][mt], bhi[u][nt]);

        __syncthreads();
        if (it + 2 < 32)
            gemm_loadslab(sb, it & 1, (it + 2) * 32, Ahi, Alo, Bhi, Blo);
    }
}

// ---------------------------------------------------------------------------
// QKV projection: scattered to [b,h,s,dk]. Logical N = 3072 (Q|K|V).
// ---------------------------------------------------------------------------
__global__ __launch_bounds__(256, 2)
void qkv_mma_kernel(const float* __restrict__ bq, const float* __restrict__ bk,
                    const float* __restrict__ bv)
{
    extern __shared__ char smem[];
    const uint32_t sb = smem_u32(smem);

    const int m0   = blockIdx.x * BM;
    const int n0g  = blockIdx.y * BN;          // 0..3071
    const int wsel = n0g >> 10;
    const int n0   = n0g & 1023;

    const float* __restrict__ bia = (wsel == 0) ? bq : ((wsel == 1) ? bk : bv);
    float* __restrict__ dst       = (wsel == 0) ? g_Q : ((wsel == 1) ? g_K : g_V);

    float acc[2][4][4];
#pragma unroll
    for (int i = 0; i < 2; i++)
#pragma unroll
        for (int j = 0; j < 4; j++)
#pragma unroll
            for (int k = 0; k < 4; k++) acc[i][j][k] = 0.f;

    gemm_mainloop(sb,
                  g_xhi + (size_t)m0 * DMODEL, g_xlo + (size_t)m0 * DMODEL,
                  g_whi + (size_t)n0g * DMODEL, g_wlo + (size_t)n0g * DMODEL,
                  acc);

    const int lane = threadIdx.x & 31;
    const int wid  = threadIdx.x >> 5;
    const int mw   = (wid & 3) * 32;
    const int nw   = (wid >> 2) * 32;

#pragma unroll
    for (int mt = 0; mt < 2; mt++) {
#pragma unroll
        for (int nt = 0; nt < 4; nt++) {
            const int n    = n0 + nw + nt * 8 + (lane & 3) * 2;
            const int head = n >> 6;
            const int dk   = n & 63;
            const float b0v = __ldg(bia + n), b1v = __ldg(bia + n + 1);
#pragma unroll
            for (int hh = 0; hh < 2; hh++) {
                const int m    = m0 + mw + mt * 16 + (lane >> 2) + hh * 8;
                const int bb   = m >> 11;
                const int srow = m & (SEQ - 1);
                float2 v = make_float2(acc[mt][nt][hh * 2] + b0v,
                                       acc[mt][nt][hh * 2 + 1] + b1v);
                *(float2*)(dst + ((size_t)((bb * NHEADS + head) * SEQ + srow)) * DK + dk) = v;
            }
        }
    }
}

// ---------------------------------------------------------------------------
// Output projection: out = ctx·Wo^T + bo  (Wo rows live at g_whi + 3072*1024)
// ---------------------------------------------------------------------------
__global__ __launch_bounds__(256, 2)
void oproj_mma_kernel(const float* __restrict__ bo, float* __restrict__ out)
{
    extern __shared__ char smem[];
    const uint32_t sb = smem_u32(smem);

    const int m0 = blockIdx.x * BM;
    const int n0 = blockIdx.y * BN;

    float acc[2][4][4];
#pragma unroll
    for (int i = 0; i < 2; i++)
#pragma unroll
        for (int j = 0; j < 4; j++)
#pragma unroll
            for (int k = 0; k < 4; k++) acc[i][j][k] = 0.f;

    gemm_mainloop(sb,
                  g_chi + (size_t)m0 * DMODEL, g_clo + (size_t)m0 * DMODEL,
                  g_whi + (size_t)(3072 + n0) * DMODEL,
                  g_wlo + (size_t)(3072 + n0) * DMODEL,
                  acc);

    const int lane = threadIdx.x & 31;
    const int wid  = threadIdx.x >> 5;
    const int mw   = (wid & 3) * 32;
    const int nw   = (wid >> 2) * 32;

#pragma unroll
    for (int mt = 0; mt < 2; mt++) {
#pragma unroll
        for (int nt = 0; nt < 4; nt++) {
            const int n = n0 + nw + nt * 8 + (lane & 3) * 2;
            const float b0v = __ldg(bo + n), b1v = __ldg(bo + n + 1);
#pragma unroll
            for (int hh = 0; hh < 2; hh++) {
                const int m = m0 + mw + mt * 16 + (lane >> 2) + hh * 8;
                float2 v = make_float2(acc[mt][nt][hh * 2] + b0v,
                                       acc[mt][nt][hh * 2 + 1] + b1v);
                *(float2*)(out + (size_t)m * DMODEL + n) = v;
            }
        }
    }
}

// ---------------------------------------------------------------------------
// Causal flash attention, fp32 (proven; HMMA port next round).
// ---------------------------------------------------------------------------
#define ASTR 65

__global__ __launch_bounds__(256)
void attn_kernel()
{
    extern __shared__ float sm[];
    float* Qs = sm;
    float* Ks = Qs + 64 * ASTR;
    float* Vs = Ks + 64 * ASTR;
    float* Ps = Vs + 64 * ASTR;

    const int bid = blockIdx.x;
    const int qb  = bid & 31;
    const int h   = (bid >> 5) & (NHEADS - 1);
    const int b   = bid >> 9;

    const int tid = threadIdx.x;
    const int tx  = tid & 15;
    const int ty  = tid >> 4;

    const size_t headbase = (size_t)(b * NHEADS + h) * SEQ * DK;
    const float* Qbase = g_Q + headbase + (size_t)qb * 64 * DK;
    const float* Kh    = g_K + headbase;
    const float* Vh    = g_V + headbase;

    for (int idx = tid; idx < 64 * 64; idx += 256) {
        const int r = idx >> 6, d = idx & 63;
        Qs[r * ASTR + d] = Qbase[r * DK + d];
    }

    float o[4][4];
    float mrow[4], lrow[4];
#pragma unroll
    for (int i = 0; i < 4; i++) {
        mrow[i] = -1e30f;
        lrow[i] = 0.f;
#pragma unroll
        for (int j = 0; j < 4; j++) o[i][j] = 0.f;
    }

    for (int jt = 0; jt <= qb; jt++) {
        __syncthreads();

        const float* Kb = Kh + (size_t)jt * 64 * DK;
        const float* Vb = Vh + (size_t)jt * 64 * DK;
        for (int idx = tid; idx < 64 * 64; idx += 256) {
            const int r = idx >> 6, d = idx & 63;
            Ks[r * ASTR + d] = Kb[r * DK + d];
            Vs[r * ASTR + d] = Vb[r * DK + d];
        }
        __syncthreads();

        float s[4][4];
#pragma unroll
        for (int i = 0; i < 4; i++)
#pragma unroll
            for (int j = 0; j < 4; j++) s[i][j] = 0.f;

#pragma unroll 16
        for (int d = 0; d < 64; d++) {
            float qv[4], kv[4];
#pragma unroll
            for (int i = 0; i < 4; i++) qv[i] = Qs[(ty * 4 + i) * ASTR + d];
#pragma unroll
            for (int j = 0; j < 4; j++) kv[j] = Ks[(tx * 4 + j) * ASTR + d];
#pragma unroll
            for (int i = 0; i < 4; i++)
#pragma unroll
                for (int j = 0; j < 4; j++)
                    s[i][j] += qv[i] * kv[j];
        }

        const float scale = 0.125f;
        if (jt == qb) {
#pragma unroll
            for (int i = 0; i < 4; i++) {
                const int qg = (qb << 6) + (ty << 2) + i;
#pragma unroll
                for (int j = 0; j < 4; j++) {
                    const int kg = (jt << 6) + (tx << 2) + j;
                    s[i][j] = (kg <= qg) ? s[i][j] * scale : -1e30f;
                }
            }
        } else {
#pragma unroll
            for (int i = 0; i < 4; i++)
#pragma unroll
                for (int j = 0; j < 4; j++) s[i][j] *= scale;
        }

        float mnew[4], alpha[4];
#pragma unroll
        for (int i = 0; i < 4; i++) {
            float v = fmaxf(fmaxf(s[i][0], s[i][1]), fmaxf(s[i][2], s[i][3]));
#pragma unroll
            for (int off = 8; off > 0; off >>= 1)
                v = fmaxf(v, __shfl_xor_sync(0xffffffffu, v, off));
            mnew[i]  = fmaxf(mrow[i], v);
            alpha[i] = __expf(mrow[i] - mnew[i]);
        }
#pragma unroll
        for (int i = 0; i < 4; i++) {
            float rs = 0.f;
#pragma unroll
            for (int j = 0; j < 4; j++) {
                const float p = __expf(s[i][j] - mnew[i]);
                s[i][j] = p;
                rs += p;
            }
#pragma unroll
            for (int off = 8; off > 0; off >>= 1)
                rs += __shfl_xor_sync(0xffffffffu, rs, off);
            lrow[i] = lrow[i] * alpha[i] + rs;
            mrow[i] = mnew[i];
#pragma unroll
            for (int j = 0; j < 4; j++) o[i][j] *= alpha[i];
        }

#pragma unroll
        for (int i = 0; i < 4; i++)
#pragma unroll
            for (int j = 0; j < 4; j++)
                Ps[(ty * 4 + i) * ASTR + tx * 4 + j] = s[i][j];
        __syncthreads();

#pragma unroll 16
        for (int kk = 0; kk < 64; kk++) {
            float pv[4], vv[4];
#pragma unroll
            for (int i = 0; i < 4; i++) pv[i] = Ps[(ty * 4 + i) * ASTR + kk];
#pragma unroll
            for (int j = 0; j < 4; j++) vv[j] = Vs[kk * ASTR + tx * 4 + j];
#pragma unroll
            for (int i = 0; i < 4; i++)
#pragma unroll
                for (int j = 0; j < 4; j++)
                    o[i][j] += pv[i] * vv[j];
        }
    }

#pragma unroll
    for (int i = 0; i < 4; i++) {
        const int r = (qb << 6) + (ty << 2) + i;
        const float inv = 1.f / lrow[i];
#pragma unroll
        for (int j = 0; j < 4; j++) {
            g_ctx[((size_t)(b * SEQ + r)) * DMODEL + h * DK + tx * 4 + j] =
                o[i][j] * inv;
        }
    }
}

// ---------------------------------------------------------------------------
extern "C" void kernel_launch(void* const* d_in, const int* in_sizes, int n_in,
                              void* d_out, int out_size)
{
    const float* x  = (const float*)d_in[0];
    // d_in[1] = mask (causal; statically known, unused)
    const float* Wq = (const float*)d_in[2];
    const float* bq = (const float*)d_in[3];
    const float* Wk = (const float*)d_in[4];
    const float* bk = (const float*)d_in[5];
    const float* Wv = (const float*)d_in[6];
    const float* bv = (const float*)d_in[7];
    const float* Wo = (const float*)d_in[8];
    const float* bo = (const float*)d_in[9];
    float* out = (float*)d_out;

    const int attn_smem = 4 * 64 * ASTR * (int)sizeof(float);   // 66560 B
    cudaFuncSetAttribute(attn_kernel,
                         cudaFuncAttributeMaxDynamicSharedMemorySize, attn_smem);
    cudaFuncSetAttribute(qkv_mma_kernel,
                         cudaFuncAttributeMaxDynamicSharedMemorySize, SMEM_G);
    cudaFuncSetAttribute(oproj_mma_kernel,
                         cudaFuncAttributeMaxDynamicSharedMemorySize, SMEM_G);

    split_x_kernel<<<(MTOT * DMODEL) / 1024, 256>>>(x);
    split_w_kernel<<<dim3((DMODEL * DMODEL) / 1024, 4), 256>>>(Wq, Wk, Wv, Wo);
    qkv_mma_kernel<<<dim3(MTOT / BM, 3 * DMODEL / BN), 256, SMEM_G>>>(bq, bk, bv);
    attn_kernel<<<BATCH * NHEADS * (SEQ / 64), 256, attn_smem>>>();
    split_ctx_kernel<<<(MTOT * DMODEL) / 1024, 256>>>();
    oproj_mma_kernel<<<dim3(MTOT / BM, DMODEL / BN), 256, SMEM_G>>>(bo, out);
}

// round 12
// speedup vs baseline: 2.5154x; 1.6152x over previous
#include <cuda_runtime.h>
#include <cstdint>

#define DMODEL 1024
#define NHEADS 16
#define DK     64
#define BATCH  2
#define SEQ    2048
#define MTOT   (BATCH * SEQ)   // 4096

// bf16 hi/lo split arrays (truncation split; 3-term scheme, proven 4.5e-5)
__device__ uint16_t g_xhi[(size_t)MTOT * DMODEL];
__device__ uint16_t g_xlo[(size_t)MTOT * DMODEL];
__device__ uint16_t g_whi[(size_t)4096 * DMODEL];   // rows: Wq|Wk|Wv|Wo
__device__ uint16_t g_wlo[(size_t)4096 * DMODEL];
__device__ uint16_t g_chi[(size_t)MTOT * DMODEL];   // attention output (ctx)
__device__ uint16_t g_clo[(size_t)MTOT * DMODEL];
// attention operands, bf16 hi/lo
__device__ uint16_t g_Qhi[(size_t)BATCH * NHEADS * SEQ * DK];
__device__ uint16_t g_Qlo[(size_t)BATCH * NHEADS * SEQ * DK];
__device__ uint16_t g_Khi[(size_t)BATCH * NHEADS * SEQ * DK];
__device__ uint16_t g_Klo[(size_t)BATCH * NHEADS * SEQ * DK];
__device__ uint16_t g_Vthi[(size_t)BATCH * NHEADS * DK * SEQ];  // transposed
__device__ uint16_t g_Vtlo[(size_t)BATCH * NHEADS * DK * SEQ];

// ===========================================================================
// Warp-level MMA plumbing (sm_80+ PTX — valid on compute_103, runs as HMMA)
// ===========================================================================
__device__ __forceinline__ uint32_t smem_u32(const void* p) {
    uint32_t a;
    asm("{ .reg .u64 t; cvta.to.shared.u64 t, %1; cvt.u32.u64 %0, t; }"
        : "=r"(a) : "l"(p));
    return a;
}

__device__ __forceinline__ void ldsm_x4(uint32_t addr, uint32_t& r0, uint32_t& r1,
                                        uint32_t& r2, uint32_t& r3) {
    asm volatile("ldmatrix.sync.aligned.m8n8.x4.shared.b16 {%0,%1,%2,%3}, [%4];"
                 : "=r"(r0), "=r"(r1), "=r"(r2), "=r"(r3) : "r"(addr));
}

__device__ __forceinline__ void ldsm_x2(uint32_t addr, uint32_t& r0, uint32_t& r1) {
    asm volatile("ldmatrix.sync.aligned.m8n8.x2.shared.b16 {%0,%1}, [%2];"
                 : "=r"(r0), "=r"(r1) : "r"(addr));
}

__device__ __forceinline__ void mma16816(float* d, const uint32_t* a,
                                         const uint32_t* b) {
    asm volatile(
        "mma.sync.aligned.m16n8k16.row.col.f32.bf16.bf16.f32 "
        "{%0,%1,%2,%3}, {%4,%5,%6,%7}, {%8,%9}, {%0,%1,%2,%3};"
        : "+f"(d[0]), "+f"(d[1]), "+f"(d[2]), "+f"(d[3])
        : "r"(a[0]), "r"(a[1]), "r"(a[2]), "r"(a[3]), "r"(b[0]), "r"(b[1]));
}

__device__ __forceinline__ void cpa16(uint32_t dst, const void* src) {
    asm volatile("cp.async.cg.shared.global [%0], [%1], 16;"
                 :: "r"(dst), "l"(src));
}
#define CP_COMMIT()  asm volatile("cp.async.commit_group;" ::: "memory")
#define CP_WAIT(N)   asm volatile("cp.async.wait_group %0;" :: "n"(N) : "memory")

__device__ __forceinline__ uint32_t prmt7632(uint32_t a, uint32_t b) {
    uint32_t r;
    asm("prmt.b32 %0, %1, %2, 0x7632;" : "=r"(r) : "r"(a), "r"(b));
    return r;
}

// pack (x,y) into bf16x2 hi + bf16x2 lo (truncation split)
__device__ __forceinline__ void split2(float x, float y, uint32_t& hp, uint32_t& lp) {
    uint32_t xi = __float_as_uint(x), yi = __float_as_uint(y);
    hp = prmt7632(xi, yi);
    float lx = x - __uint_as_float(xi & 0xffff0000u);
    float ly = y - __uint_as_float(yi & 0xffff0000u);
    lp = prmt7632(__float_as_uint(lx), __float_as_uint(ly));
}

__device__ __forceinline__ void split4(float4 v, uint32_t& h0, uint32_t& h1,
                                       uint32_t& l0, uint32_t& l1) {
    split2(v.x, v.y, h0, l0);
    split2(v.z, v.w, h1, l1);
}

__device__ __forceinline__ uint16_t bfhi(float v) {
    return (uint16_t)(__float_as_uint(v) >> 16);
}
__device__ __forceinline__ uint16_t bflo(float v) {
    float t = __uint_as_float(__float_as_uint(v) & 0xffff0000u);
    return (uint16_t)(__float_as_uint(v - t) >> 16);
}

// ===========================================================================
// Split precompute kernels (gmem fp32 -> bf16 hi/lo)
// ===========================================================================
__global__ __launch_bounds__(256)
void split_x_kernel(const float* __restrict__ x)
{
    const size_t e = ((size_t)blockIdx.x * 256 + threadIdx.x) * 4;
    float4 v = *(const float4*)(x + e);
    uint32_t h0, h1, l0, l1;
    split4(v, h0, h1, l0, l1);
    *(uint2*)(g_xhi + e) = make_uint2(h0, h1);
    *(uint2*)(g_xlo + e) = make_uint2(l0, l1);
}

__global__ __launch_bounds__(256)
void split_w_kernel(const float* __restrict__ Wq, const float* __restrict__ Wk,
                    const float* __restrict__ Wv, const float* __restrict__ Wo)
{
    const int wsel = blockIdx.y;
    const float* src = (wsel == 0) ? Wq : (wsel == 1) ? Wk : (wsel == 2) ? Wv : Wo;
    const size_t e = ((size_t)blockIdx.x * 256 + threadIdx.x) * 4;
    float4 v = *(const float4*)(src + e);
    uint32_t h0, h1, l0, l1;
    split4(v, h0, h1, l0, l1);
    const size_t d = (size_t)wsel * DMODEL * DMODEL + e;
    *(uint2*)(g_whi + d) = make_uint2(h0, h1);
    *(uint2*)(g_wlo + d) = make_uint2(l0, l1);
}

// ===========================================================================
// HMMA GEMM mainloop (proven R10): C[128x64] = A[128,1024]·B[64,1024]^T
// ===========================================================================
#define BM      128
#define BN      64
#define ROWPB   144
#define ABYTES  (BM * ROWPB)
#define BUFB    ((BM + BN) * ROWPB)
#define SMEM_G  (2 * BUFB)

__device__ __forceinline__ void gemm_loadslab(uint32_t sb, int buf, int k0,
                                              const uint16_t* __restrict__ Ahi,
                                              const uint16_t* __restrict__ Alo,
                                              const uint16_t* __restrict__ Bhi,
                                              const uint16_t* __restrict__ Blo)
{
    const int tid = threadIdx.x;
    const uint32_t base = sb + buf * BUFB;
    if (tid < 128) {
        const int r = tid;
        const uint16_t* hs = Ahi + (size_t)r * DMODEL + k0;
        const uint16_t* ls = Alo + (size_t)r * DMODEL + k0;
        const uint32_t d = base + r * ROWPB;
#pragma unroll
        for (int c = 0; c < 4; c++) {
            cpa16(d + c * 16,      hs + c * 8);
            cpa16(d + 64 + c * 16, ls + c * 8);
        }
    } else {
        const int t = tid - 128;
        const int r = t >> 1, h = t & 1;
        const uint16_t* hs = Bhi + (size_t)r * DMODEL + k0 + h * 16;
        const uint16_t* ls = Blo + (size_t)r * DMODEL + k0 + h * 16;
        const uint32_t d = base + ABYTES + r * ROWPB + h * 32;
#pragma unroll
        for (int c = 0; c < 2; c++) {
            cpa16(d + c * 16,      hs + c * 8);
            cpa16(d + 64 + c * 16, ls + c * 8);
        }
    }
    CP_COMMIT();
}

__device__ __forceinline__ void gemm_mainloop(uint32_t sb,
                                              const uint16_t* __restrict__ Ahi,
                                              const uint16_t* __restrict__ Alo,
                                              const uint16_t* __restrict__ Bhi,
                                              const uint16_t* __restrict__ Blo,
                                              float acc[2][4][4])
{
    const int tid  = threadIdx.x;
    const int lane = tid & 31;
    const int wid  = tid >> 5;
    const int mw   = (wid & 3) * 32;
    const int nw   = (wid >> 2) * 32;

    const uint32_t aoff = (uint32_t)((mw + (lane & 15)) * ROWPB + (lane >> 4) * 16);
    const uint32_t boff = (uint32_t)((nw + (lane & 7)) * ROWPB + ((lane >> 3) & 1) * 16);

    gemm_loadslab(sb, 0, 0, Ahi, Alo, Bhi, Blo);
    gemm_loadslab(sb, 1, 32, Ahi, Alo, Bhi, Blo);

#pragma unroll 1
    for (int it = 0; it < 32; ++it) {
        if (it == 31) { CP_WAIT(0); } else { CP_WAIT(1); }
        __syncthreads();

        const uint32_t bA = sb + (it & 1) * BUFB;
        const uint32_t bB = bA + ABYTES;

        uint32_t ahi[2][2][4], bhi[2][4][2], blo[2][4][2];
#pragma unroll
        for (int u = 0; u < 2; u++)
#pragma unroll
            for (int mt = 0; mt < 2; mt++)
                ldsm_x4(bA + aoff + (uint32_t)(mt * 16 * ROWPB + u * 32),
                        ahi[u][mt][0], ahi[u][mt][1], ahi[u][mt][2], ahi[u][mt][3]);
#pragma unroll
        for (int u = 0; u < 2; u++)
#pragma unroll
            for (int nt = 0; nt < 4; nt++)
                ldsm_x2(bB + boff + (uint32_t)(nt * 8 * ROWPB + u * 32),
                        bhi[u][nt][0], bhi[u][nt][1]);
#pragma unroll
        for (int u = 0; u < 2; u++)
#pragma unroll
            for (int mt = 0; mt < 2; mt++)
#pragma unroll
                for (int nt = 0; nt < 4; nt++)
                    mma16816(acc[mt][nt], ahi[u][mt], bhi[u][nt]);
#pragma unroll
        for (int u = 0; u < 2; u++)
#pragma unroll
            for (int nt = 0; nt < 4; nt++)
                ldsm_x2(bB + boff + (uint32_t)(nt * 8 * ROWPB + u * 32 + 64),
                        blo[u][nt][0], blo[u][nt][1]);
#pragma unroll
        for (int u = 0; u < 2; u++)
#pragma unroll
            for (int mt = 0; mt < 2; mt++)
#pragma unroll
                for (int nt = 0; nt < 4; nt++)
                    mma16816(acc[mt][nt], ahi[u][mt], blo[u][nt]);
#pragma unroll
        for (int u = 0; u < 2; u++)
#pragma unroll
            for (int mt = 0; mt < 2; mt++)
                ldsm_x4(bA + aoff + (uint32_t)(mt * 16 * ROWPB + u * 32 + 64),
                        ahi[u][mt][0], ahi[u][mt][1], ahi[u][mt][2], ahi[u][mt][3]);
#pragma unroll
        for (int u = 0; u < 2; u++)
#pragma unroll
            for (int mt = 0; mt < 2; mt++)
#pragma unroll
                for (int nt = 0; nt < 4; nt++)
                    mma16816(acc[mt][nt], ahi[u][mt], bhi[u][nt]);

        __syncthreads();
        if (it + 2 < 32)
            gemm_loadslab(sb, it & 1, (it + 2) * 32, Ahi, Alo, Bhi, Blo);
    }
}

// ---------------------------------------------------------------------------
// QKV projection: epilogue writes bf16 hi/lo. Q,K -> [b,h,s,dk]; V -> [b,h,dk,s].
// ---------------------------------------------------------------------------
__global__ __launch_bounds__(256, 2)
void qkv_mma_kernel(const float* __restrict__ bq, const float* __restrict__ bk,
                    const float* __restrict__ bv)
{
    extern __shared__ char smem[];
    const uint32_t sb = smem_u32(smem);

    const int m0   = blockIdx.x * BM;
    const int n0g  = blockIdx.y * BN;
    const int wsel = n0g >> 10;
    const int n0   = n0g & 1023;

    const float* __restrict__ bia = (wsel == 0) ? bq : ((wsel == 1) ? bk : bv);

    float acc[2][4][4];
#pragma unroll
    for (int i = 0; i < 2; i++)
#pragma unroll
        for (int j = 0; j < 4; j++)
#pragma unroll
            for (int k = 0; k < 4; k++) acc[i][j][k] = 0.f;

    gemm_mainloop(sb,
                  g_xhi + (size_t)m0 * DMODEL, g_xlo + (size_t)m0 * DMODEL,
                  g_whi + (size_t)n0g * DMODEL, g_wlo + (size_t)n0g * DMODEL,
                  acc);

    const int lane = threadIdx.x & 31;
    const int wid  = threadIdx.x >> 5;
    const int mw   = (wid & 3) * 32;
    const int nw   = (wid >> 2) * 32;

#pragma unroll
    for (int mt = 0; mt < 2; mt++) {
#pragma unroll
        for (int nt = 0; nt < 4; nt++) {
            const int n    = n0 + nw + nt * 8 + (lane & 3) * 2;
            const int head = n >> 6;
            const int dk   = n & 63;
            const float b0v = __ldg(bia + n), b1v = __ldg(bia + n + 1);
#pragma unroll
            for (int hh = 0; hh < 2; hh++) {
                const int m    = m0 + mw + mt * 16 + (lane >> 2) + hh * 8;
                const int bb   = m >> 11;
                const int srow = m & (SEQ - 1);
                const float v0 = acc[mt][nt][hh * 2] + b0v;
                const float v1 = acc[mt][nt][hh * 2 + 1] + b1v;
                const int bh   = bb * NHEADS + head;
                if (wsel < 2) {
                    uint16_t* dh = wsel ? g_Khi : g_Qhi;
                    uint16_t* dl = wsel ? g_Klo : g_Qlo;
                    uint32_t hp, lp;
                    split2(v0, v1, hp, lp);
                    const size_t idx = ((size_t)bh * SEQ + srow) * DK + dk;
                    *(uint32_t*)(dh + idx) = hp;
                    *(uint32_t*)(dl + idx) = lp;
                } else {
                    const size_t base = (size_t)bh * DK;
                    g_Vthi[(base + dk) * SEQ + srow]     = bfhi(v0);
                    g_Vtlo[(base + dk) * SEQ + srow]     = bflo(v0);
                    g_Vthi[(base + dk + 1) * SEQ + srow] = bfhi(v1);
                    g_Vtlo[(base + dk + 1) * SEQ + srow] = bflo(v1);
                }
            }
        }
    }
}

// ---------------------------------------------------------------------------
// Output projection: out = ctx·Wo^T + bo   (ctx from g_chi/g_clo)
// ---------------------------------------------------------------------------
__global__ __launch_bounds__(256, 2)
void oproj_mma_kernel(const float* __restrict__ bo, float* __restrict__ out)
{
    extern __shared__ char smem[];
    const uint32_t sb = smem_u32(smem);

    const int m0 = blockIdx.x * BM;
    const int n0 = blockIdx.y * BN;

    float acc[2][4][4];
#pragma unroll
    for (int i = 0; i < 2; i++)
#pragma unroll
        for (int j = 0; j < 4; j++)
#pragma unroll
            for (int k = 0; k < 4; k++) acc[i][j][k] = 0.f;

    gemm_mainloop(sb,
                  g_chi + (size_t)m0 * DMODEL, g_clo + (size_t)m0 * DMODEL,
                  g_whi + (size_t)(3072 + n0) * DMODEL,
                  g_wlo + (size_t)(3072 + n0) * DMODEL,
                  acc);

    const int lane = threadIdx.x & 31;
    const int wid  = threadIdx.x >> 5;
    const int mw   = (wid & 3) * 32;
    const int nw   = (wid >> 2) * 32;

#pragma unroll
    for (int mt = 0; mt < 2; mt++) {
#pragma unroll
        for (int nt = 0; nt < 4; nt++) {
            const int n = n0 + nw + nt * 8 + (lane & 3) * 2;
            const float b0v = __ldg(bo + n), b1v = __ldg(bo + n + 1);
#pragma unroll
            for (int hh = 0; hh < 2; hh++) {
                const int m = m0 + mw + mt * 16 + (lane >> 2) + hh * 8;
                float2 v = make_float2(acc[mt][nt][hh * 2] + b0v,
                                       acc[mt][nt][hh * 2 + 1] + b1v);
                *(float2*)(out + (size_t)m * DMODEL + n) = v;
            }
        }
    }
}

// ===========================================================================
// HMMA causal flash attention. Block = (b, h, 128-query tile); 8 warps x 16 rows.
// S = Q·K^T (3-term split, fp32 acc); online softmax in registers; P split
// hi/lo in registers -> P·V (3-term) with V^T tiles (plain ldsm_x2 B frags).
// K/V^T tiles double-buffered via cp.async.
// ===========================================================================
#define APITCH 272                 // 64 hi (128B) + 64 lo (128B) + 16 pad
#define KTILEB (64 * APITCH)       // 17408
#define KVBUF  (2 * KTILEB)        // 34816 (K tile + V tile)
#define ATTN_SMEM (2 * KVBUF)      // 69632

__device__ __forceinline__ void attn_load_tile(uint32_t dst,
    const uint16_t* __restrict__ Khi, const uint16_t* __restrict__ Klo,
    const uint16_t* __restrict__ Vthi, const uint16_t* __restrict__ Vtlo, int k0)
{
    const int t = threadIdx.x;
    const int r = t >> 2, part = t & 3;
    {   // K tile: rows = keys, cols = dk
        const uint16_t* hs = Khi + (size_t)(k0 + r) * DK + part * 16;
        const uint16_t* ls = Klo + (size_t)(k0 + r) * DK + part * 16;
        const uint32_t d = dst + r * APITCH + part * 32;
        cpa16(d, hs);        cpa16(d + 16, hs + 8);
        cpa16(d + 128, ls);  cpa16(d + 144, ls + 8);
    }
    {   // V^T tile: rows = dk, cols = keys
        const uint16_t* hs = Vthi + (size_t)r * SEQ + k0 + part * 16;
        const uint16_t* ls = Vtlo + (size_t)r * SEQ + k0 + part * 16;
        const uint32_t d = dst + KTILEB + r * APITCH + part * 32;
        cpa16(d, hs);        cpa16(d + 16, hs + 8);
        cpa16(d + 128, ls);  cpa16(d + 144, ls + 8);
    }
    CP_COMMIT();
}

__global__ __launch_bounds__(256)
void attn_mma_kernel()
{
    extern __shared__ char smem[];
    const uint32_t sb = smem_u32(smem);

    const int bid = blockIdx.x;
    const int qt  = bid & 15;
    const int h   = (bid >> 4) & (NHEADS - 1);
    const int b   = bid >> 8;
    const int bh  = b * NHEADS + h;
    const int q0  = qt * 128;

    const int tid = threadIdx.x, lane = tid & 31, w = tid >> 5;

    const uint16_t* Qhi  = g_Qhi  + (size_t)bh * SEQ * DK;
    const uint16_t* Qlo  = g_Qlo  + (size_t)bh * SEQ * DK;
    const uint16_t* Khi  = g_Khi  + (size_t)bh * SEQ * DK;
    const uint16_t* Klo  = g_Klo  + (size_t)bh * SEQ * DK;
    const uint16_t* Vthi = g_Vthi + (size_t)bh * DK * SEQ;
    const uint16_t* Vtlo = g_Vtlo + (size_t)bh * DK * SEQ;

    // ---- stage Q tile (128 x 64 hi+lo) into smem, then to registers ----
    {
        const int r = tid >> 1, seg = tid & 1;
        const uint16_t* hs = Qhi + (size_t)(q0 + r) * DK + seg * 32;
        const uint16_t* ls = Qlo + (size_t)(q0 + r) * DK + seg * 32;
        const uint32_t d = sb + r * APITCH + seg * 64;
#pragma unroll
        for (int c = 0; c < 4; c++) {
            cpa16(d + c * 16,       hs + c * 8);
            cpa16(d + 128 + c * 16, ls + c * 8);
        }
    }
    CP_COMMIT(); CP_WAIT(0); __syncthreads();

    uint32_t qh[4][4], ql[4][4];
    {
        const uint32_t aoffQ = sb +
            (uint32_t)((w * 16 + (lane & 15)) * APITCH + (lane >> 4) * 16);
#pragma unroll
        for (int ks = 0; ks < 4; ks++) {
            ldsm_x4(aoffQ + ks * 32,       qh[ks][0], qh[ks][1], qh[ks][2], qh[ks][3]);
            ldsm_x4(aoffQ + ks * 32 + 128, ql[ks][0], ql[ks][1], ql[ks][2], ql[ks][3]);
        }
    }
    __syncthreads();   // Q area becomes K/V buffer 0

    float o[8][4];
#pragma unroll
    for (int i = 0; i < 8; i++)
#pragma unroll
        for (int j = 0; j < 4; j++) o[i][j] = 0.f;
    float m0 = -1e30f, m1 = -1e30f, l0 = 0.f, l1 = 0.f;

    const int jtmax = 2 * qt + 1;
    attn_load_tile(sb, Khi, Klo, Vthi, Vtlo, 0);

    const uint32_t boffB = (uint32_t)((lane & 7) * APITCH + ((lane >> 3) & 1) * 16);

#pragma unroll 1
    for (int jt = 0; jt <= jtmax; jt++) {
        if (jt < jtmax) {
            attn_load_tile(sb + ((jt + 1) & 1) * KVBUF, Khi, Klo, Vthi, Vtlo,
                           (jt + 1) * 64);
            CP_WAIT(1);
        } else {
            CP_WAIT(0);
        }
        __syncthreads();

        const uint32_t bK = sb + (jt & 1) * KVBUF;
        const uint32_t bV = bK + KTILEB;

        // ---- S = Q K^T (3-term) ----
        float s[8][4];
#pragma unroll
        for (int i = 0; i < 8; i++)
#pragma unroll
            for (int j = 0; j < 4; j++) s[i][j] = 0.f;

#pragma unroll
        for (int ks = 0; ks < 4; ks++) {
            uint32_t kb[8][2], kl[8][2];
#pragma unroll
            for (int nt = 0; nt < 8; nt++)
                ldsm_x2(bK + boffB + (uint32_t)(nt * 8 * APITCH + ks * 32),
                        kb[nt][0], kb[nt][1]);
#pragma unroll
            for (int nt = 0; nt < 8; nt++) mma16816(s[nt], qh[ks], kb[nt]);
#pragma unroll
            for (int nt = 0; nt < 8; nt++) mma16816(s[nt], ql[ks], kb[nt]);
#pragma unroll
            for (int nt = 0; nt < 8; nt++)
                ldsm_x2(bK + boffB + (uint32_t)(nt * 8 * APITCH + ks * 32 + 128),
                        kl[nt][0], kl[nt][1]);
#pragma unroll
            for (int nt = 0; nt < 8; nt++) mma16816(s[nt], qh[ks], kl[nt]);
        }

        // ---- scale + causal mask ----
        const int r0 = q0 + w * 16 + (lane >> 2);
        if (jt >= 2 * qt) {
#pragma unroll
            for (int nt = 0; nt < 8; nt++) {
                const int kg = jt * 64 + nt * 8 + (lane & 3) * 2;
#pragma unroll
                for (int e = 0; e < 4; e++) {
                    const int kge = kg + (e & 1);
                    const int qge = r0 + ((e >> 1) << 3);
                    s[nt][e] = (kge <= qge) ? s[nt][e] * 0.125f : -1e30f;
                }
            }
        } else {
#pragma unroll
            for (int nt = 0; nt < 8; nt++)
#pragma unroll
                for (int e = 0; e < 4; e++) s[nt][e] *= 0.125f;
        }

        // ---- online softmax (rows r0, r0+8) ----
        float mx0 = -1e30f, mx1 = -1e30f;
#pragma unroll
        for (int nt = 0; nt < 8; nt++) {
            mx0 = fmaxf(mx0, fmaxf(s[nt][0], s[nt][1]));
            mx1 = fmaxf(mx1, fmaxf(s[nt][2], s[nt][3]));
        }
        mx0 = fmaxf(mx0, __shfl_xor_sync(0xffffffffu, mx0, 1));
        mx0 = fmaxf(mx0, __shfl_xor_sync(0xffffffffu, mx0, 2));
        mx1 = fmaxf(mx1, __shfl_xor_sync(0xffffffffu, mx1, 1));
        mx1 = fmaxf(mx1, __shfl_xor_sync(0xffffffffu, mx1, 2));
        const float mn0 = fmaxf(m0, mx0), mn1 = fmaxf(m1, mx1);
        const float a0 = __expf(m0 - mn0), a1 = __expf(m1 - mn1);
        m0 = mn0; m1 = mn1;
        float rs0 = 0.f, rs1 = 0.f;
#pragma unroll
        for (int nt = 0; nt < 8; nt++) {
            s[nt][0] = __expf(s[nt][0] - mn0); rs0 += s[nt][0];
            s[nt][1] = __expf(s[nt][1] - mn0); rs0 += s[nt][1];
            s[nt][2] = __expf(s[nt][2] - mn1); rs1 += s[nt][2];
            s[nt][3] = __expf(s[nt][3] - mn1); rs1 += s[nt][3];
        }
        rs0 += __shfl_xor_sync(0xffffffffu, rs0, 1);
        rs0 += __shfl_xor_sync(0xffffffffu, rs0, 2);
        rs1 += __shfl_xor_sync(0xffffffffu, rs1, 1);
        rs1 += __shfl_xor_sync(0xffffffffu, rs1, 2);
        l0 = l0 * a0 + rs0;
        l1 = l1 * a1 + rs1;
#pragma unroll
        for (int nt = 0; nt < 8; nt++) {
            o[nt][0] *= a0; o[nt][1] *= a0; o[nt][2] *= a1; o[nt][3] *= a1;
        }

        // ---- O += P V  (P frags from S registers; 3-term) ----
#pragma unroll
        for (int ks2 = 0; ks2 < 4; ks2++) {
            uint32_t ph[4], pl[4];
            split2(s[2 * ks2][0],     s[2 * ks2][1],     ph[0], pl[0]);
            split2(s[2 * ks2][2],     s[2 * ks2][3],     ph[1], pl[1]);
            split2(s[2 * ks2 + 1][0], s[2 * ks2 + 1][1], ph[2], pl[2]);
            split2(s[2 * ks2 + 1][2], s[2 * ks2 + 1][3], ph[3], pl[3]);
            uint32_t vh[8][2], vl[8][2];
#pragma unroll
            for (int nt = 0; nt < 8; nt++)
                ldsm_x2(bV + boffB + (uint32_t)(nt * 8 * APITCH + ks2 * 32),
                        vh[nt][0], vh[nt][1]);
#pragma unroll
            for (int nt = 0; nt < 8; nt++) mma16816(o[nt], ph, vh[nt]);
#pragma unroll
            for (int nt = 0; nt < 8; nt++) mma16816(o[nt], pl, vh[nt]);
#pragma unroll
            for (int nt = 0; nt < 8; nt++)
                ldsm_x2(bV + boffB + (uint32_t)(nt * 8 * APITCH + ks2 * 32 + 128),
                        vl[nt][0], vl[nt][1]);
#pragma unroll
            for (int nt = 0; nt < 8; nt++) mma16816(o[nt], ph, vl[nt]);
        }

        __syncthreads();
    }

    // ---- epilogue: normalize and write ctx hi/lo ----
    const float i0 = 1.f / l0, i1 = 1.f / l1;
    const int rq = q0 + w * 16 + (lane >> 2);
    const size_t row0 = (size_t)(b * SEQ + rq) * DMODEL + h * DK;
    const size_t row1 = row0 + (size_t)8 * DMODEL;
#pragma unroll
    for (int nt = 0; nt < 8; nt++) {
        const int c = nt * 8 + (lane & 3) * 2;
        uint32_t hp, lp;
        split2(o[nt][0] * i0, o[nt][1] * i0, hp, lp);
        *(uint32_t*)(g_chi + row0 + c) = hp;
        *(uint32_t*)(g_clo + row0 + c) = lp;
        split2(o[nt][2] * i1, o[nt][3] * i1, hp, lp);
        *(uint32_t*)(g_chi + row1 + c) = hp;
        *(uint32_t*)(g_clo + row1 + c) = lp;
    }
}

// ---------------------------------------------------------------------------
extern "C" void kernel_launch(void* const* d_in, const int* in_sizes, int n_in,
                              void* d_out, int out_size)
{
    const float* x  = (const float*)d_in[0];
    // d_in[1] = mask (causal; statically known, unused)
    const float* Wq = (const float*)d_in[2];
    const float* bq = (const float*)d_in[3];
    const float* Wk = (const float*)d_in[4];
    const float* bk = (const float*)d_in[5];
    const float* Wv = (const float*)d_in[6];
    const float* bv = (const float*)d_in[7];
    const float* Wo = (const float*)d_in[8];
    const float* bo = (const float*)d_in[9];
    float* out = (float*)d_out;

    cudaFuncSetAttribute(qkv_mma_kernel,
                         cudaFuncAttributeMaxDynamicSharedMemorySize, SMEM_G);
    cudaFuncSetAttribute(oproj_mma_kernel,
                         cudaFuncAttributeMaxDynamicSharedMemorySize, SMEM_G);
    cudaFuncSetAttribute(attn_mma_kernel,
                         cudaFuncAttributeMaxDynamicSharedMemorySize, ATTN_SMEM);

    split_x_kernel<<<(MTOT * DMODEL) / 1024, 256>>>(x);
    split_w_kernel<<<dim3((DMODEL * DMODEL) / 1024, 4), 256>>>(Wq, Wk, Wv, Wo);
    qkv_mma_kernel<<<dim3(MTOT / BM, 3 * DMODEL / BN), 256, SMEM_G>>>(bq, bk, bv);
    attn_mma_kernel<<<BATCH * NHEADS * (SEQ / 128), 256, ATTN_SMEM>>>();
    oproj_mma_kernel<<<dim3(MTOT / BM, DMODEL / BN), 256, SMEM_G>>>(bo, out);
}

// round 13
// speedup vs baseline: 2.5340x; 1.0074x over previous
#include <cuda_runtime.h>
#include <cstdint>

#define DMODEL 1024
#define NHEADS 16
#define DK     64
#define BATCH  2
#define SEQ    2048
#define MTOT   (BATCH * SEQ)   // 4096

// bf16 hi/lo split arrays (truncation split; 3-term scheme, proven 4.5e-5)
__device__ uint16_t g_xhi[(size_t)MTOT * DMODEL];
__device__ uint16_t g_xlo[(size_t)MTOT * DMODEL];
__device__ uint16_t g_whi[(size_t)4096 * DMODEL];   // rows: Wq|Wk|Wv|Wo
__device__ uint16_t g_wlo[(size_t)4096 * DMODEL];
__device__ uint16_t g_chi[(size_t)MTOT * DMODEL];   // attention output (ctx)
__device__ uint16_t g_clo[(size_t)MTOT * DMODEL];
// attention operands, bf16 hi/lo, all [b,h,s,dk]
__device__ uint16_t g_Qhi[(size_t)BATCH * NHEADS * SEQ * DK];
__device__ uint16_t g_Qlo[(size_t)BATCH * NHEADS * SEQ * DK];
__device__ uint16_t g_Khi[(size_t)BATCH * NHEADS * SEQ * DK];
__device__ uint16_t g_Klo[(size_t)BATCH * NHEADS * SEQ * DK];
__device__ uint16_t g_Vhi[(size_t)BATCH * NHEADS * SEQ * DK];
__device__ uint16_t g_Vlo[(size_t)BATCH * NHEADS * SEQ * DK];

// ===========================================================================
// Warp-level MMA plumbing (sm_80+ PTX — valid on compute_103, runs as HMMA)
// ===========================================================================
__device__ __forceinline__ uint32_t smem_u32(const void* p) {
    uint32_t a;
    asm("{ .reg .u64 t; cvta.to.shared.u64 t, %1; cvt.u32.u64 %0, t; }"
        : "=r"(a) : "l"(p));
    return a;
}

__device__ __forceinline__ void ldsm_x4(uint32_t addr, uint32_t& r0, uint32_t& r1,
                                        uint32_t& r2, uint32_t& r3) {
    asm volatile("ldmatrix.sync.aligned.m8n8.x4.shared.b16 {%0,%1,%2,%3}, [%4];"
                 : "=r"(r0), "=r"(r1), "=r"(r2), "=r"(r3) : "r"(addr));
}

__device__ __forceinline__ void ldsm_x2(uint32_t addr, uint32_t& r0, uint32_t& r1) {
    asm volatile("ldmatrix.sync.aligned.m8n8.x2.shared.b16 {%0,%1}, [%2];"
                 : "=r"(r0), "=r"(r1) : "r"(addr));
}

__device__ __forceinline__ void ldsm_x2t(uint32_t addr, uint32_t& r0, uint32_t& r1) {
    asm volatile("ldmatrix.sync.aligned.m8n8.x2.trans.shared.b16 {%0,%1}, [%2];"
                 : "=r"(r0), "=r"(r1) : "r"(addr));
}

__device__ __forceinline__ void mma16816(float* d, const uint32_t* a,
                                         const uint32_t* b) {
    asm volatile(
        "mma.sync.aligned.m16n8k16.row.col.f32.bf16.bf16.f32 "
        "{%0,%1,%2,%3}, {%4,%5,%6,%7}, {%8,%9}, {%0,%1,%2,%3};"
        : "+f"(d[0]), "+f"(d[1]), "+f"(d[2]), "+f"(d[3])
        : "r"(a[0]), "r"(a[1]), "r"(a[2]), "r"(a[3]), "r"(b[0]), "r"(b[1]));
}

__device__ __forceinline__ void cpa16(uint32_t dst, const void* src) {
    asm volatile("cp.async.cg.shared.global [%0], [%1], 16;"
                 :: "r"(dst), "l"(src));
}
#define CP_COMMIT()  asm volatile("cp.async.commit_group;" ::: "memory")
#define CP_WAIT(N)   asm volatile("cp.async.wait_group %0;" :: "n"(N) : "memory")

__device__ __forceinline__ uint32_t prmt7632(uint32_t a, uint32_t b) {
    uint32_t r;
    asm("prmt.b32 %0, %1, %2, 0x7632;" : "=r"(r) : "r"(a), "r"(b));
    return r;
}

__device__ __forceinline__ void split2(float x, float y, uint32_t& hp, uint32_t& lp) {
    uint32_t xi = __float_as_uint(x), yi = __float_as_uint(y);
    hp = prmt7632(xi, yi);
    float lx = x - __uint_as_float(xi & 0xffff0000u);
    float ly = y - __uint_as_float(yi & 0xffff0000u);
    lp = prmt7632(__float_as_uint(lx), __float_as_uint(ly));
}

__device__ __forceinline__ void split4(float4 v, uint32_t& h0, uint32_t& h1,
                                       uint32_t& l0, uint32_t& l1) {
    split2(v.x, v.y, h0, l0);
    split2(v.z, v.w, h1, l1);
}

// ===========================================================================
// Split precompute kernels (gmem fp32 -> bf16 hi/lo)
// ===========================================================================
__global__ __launch_bounds__(256)
void split_x_kernel(const float* __restrict__ x)
{
    const size_t e = ((size_t)blockIdx.x * 256 + threadIdx.x) * 4;
    float4 v = *(const float4*)(x + e);
    uint32_t h0, h1, l0, l1;
    split4(v, h0, h1, l0, l1);
    *(uint2*)(g_xhi + e) = make_uint2(h0, h1);
    *(uint2*)(g_xlo + e) = make_uint2(l0, l1);
}

__global__ __launch_bounds__(256)
void split_w_kernel(const float* __restrict__ Wq, const float* __restrict__ Wk,
                    const float* __restrict__ Wv, const float* __restrict__ Wo)
{
    const int wsel = blockIdx.y;
    const float* src = (wsel == 0) ? Wq : (wsel == 1) ? Wk : (wsel == 2) ? Wv : Wo;
    const size_t e = ((size_t)blockIdx.x * 256 + threadIdx.x) * 4;
    float4 v = *(const float4*)(src + e);
    uint32_t h0, h1, l0, l1;
    split4(v, h0, h1, l0, l1);
    const size_t d = (size_t)wsel * DMODEL * DMODEL + e;
    *(uint2*)(g_whi + d) = make_uint2(h0, h1);
    *(uint2*)(g_wlo + d) = make_uint2(l0, l1);
}

// ===========================================================================
// HMMA GEMM mainloop (proven R10): C[128x64] = A[128,1024]·B[64,1024]^T
// ===========================================================================
#define BM      128
#define BN      64
#define ROWPB   144
#define ABYTES  (BM * ROWPB)
#define BUFB    ((BM + BN) * ROWPB)
#define SMEM_G  (2 * BUFB)

__device__ __forceinline__ void gemm_loadslab(uint32_t sb, int buf, int k0,
                                              const uint16_t* __restrict__ Ahi,
                                              const uint16_t* __restrict__ Alo,
                                              const uint16_t* __restrict__ Bhi,
                                              const uint16_t* __restrict__ Blo)
{
    const int tid = threadIdx.x;
    const uint32_t base = sb + buf * BUFB;
    if (tid < 128) {
        const int r = tid;
        const uint16_t* hs = Ahi + (size_t)r * DMODEL + k0;
        const uint16_t* ls = Alo + (size_t)r * DMODEL + k0;
        const uint32_t d = base + r * ROWPB;
#pragma unroll
        for (int c = 0; c < 4; c++) {
            cpa16(d + c * 16,      hs + c * 8);
            cpa16(d + 64 + c * 16, ls + c * 8);
        }
    } else {
        const int t = tid - 128;
        const int r = t >> 1, h = t & 1;
        const uint16_t* hs = Bhi + (size_t)r * DMODEL + k0 + h * 16;
        const uint16_t* ls = Blo + (size_t)r * DMODEL + k0 + h * 16;
        const uint32_t d = base + ABYTES + r * ROWPB + h * 32;
#pragma unroll
        for (int c = 0; c < 2; c++) {
            cpa16(d + c * 16,      hs + c * 8);
            cpa16(d + 64 + c * 16, ls + c * 8);
        }
    }
    CP_COMMIT();
}

__device__ __forceinline__ void gemm_mainloop(uint32_t sb,
                                              const uint16_t* __restrict__ Ahi,
                                              const uint16_t* __restrict__ Alo,
                                              const uint16_t* __restrict__ Bhi,
                                              const uint16_t* __restrict__ Blo,
                                              float acc[2][4][4])
{
    const int tid  = threadIdx.x;
    const int lane = tid & 31;
    const int wid  = tid >> 5;
    const int mw   = (wid & 3) * 32;
    const int nw   = (wid >> 2) * 32;

    const uint32_t aoff = (uint32_t)((mw + (lane & 15)) * ROWPB + (lane >> 4) * 16);
    const uint32_t boff = (uint32_t)((nw + (lane & 7)) * ROWPB + ((lane >> 3) & 1) * 16);

    gemm_loadslab(sb, 0, 0, Ahi, Alo, Bhi, Blo);
    gemm_loadslab(sb, 1, 32, Ahi, Alo, Bhi, Blo);

#pragma unroll 1
    for (int it = 0; it < 32; ++it) {
        if (it == 31) { CP_WAIT(0); } else { CP_WAIT(1); }
        __syncthreads();

        const uint32_t bA = sb + (it & 1) * BUFB;
        const uint32_t bB = bA + ABYTES;

        uint32_t ahi[2][2][4], bhi[2][4][2], blo[2][4][2];
#pragma unroll
        for (int u = 0; u < 2; u++)
#pragma unroll
            for (int mt = 0; mt < 2; mt++)
                ldsm_x4(bA + aoff + (uint32_t)(mt * 16 * ROWPB + u * 32),
                        ahi[u][mt][0], ahi[u][mt][1], ahi[u][mt][2], ahi[u][mt][3]);
#pragma unroll
        for (int u = 0; u < 2; u++)
#pragma unroll
            for (int nt = 0; nt < 4; nt++)
                ldsm_x2(bB + boff + (uint32_t)(nt * 8 * ROWPB + u * 32),
                        bhi[u][nt][0], bhi[u][nt][1]);
#pragma unroll
        for (int u = 0; u < 2; u++)
#pragma unroll
            for (int mt = 0; mt < 2; mt++)
#pragma unroll
                for (int nt = 0; nt < 4; nt++)
                    mma16816(acc[mt][nt], ahi[u][mt], bhi[u][nt]);
#pragma unroll
        for (int u = 0; u < 2; u++)
#pragma unroll
            for (int nt = 0; nt < 4; nt++)
                ldsm_x2(bB + boff + (uint32_t)(nt * 8 * ROWPB + u * 32 + 64),
                        blo[u][nt][0], blo[u][nt][1]);
#pragma unroll
        for (int u = 0; u < 2; u++)
#pragma unroll
            for (int mt = 0; mt < 2; mt++)
#pragma unroll
                for (int nt = 0; nt < 4; nt++)
                    mma16816(acc[mt][nt], ahi[u][mt], blo[u][nt]);
#pragma unroll
        for (int u = 0; u < 2; u++)
#pragma unroll
            for (int mt = 0; mt < 2; mt++)
                ldsm_x4(bA + aoff + (uint32_t)(mt * 16 * ROWPB + u * 32 + 64),
                        ahi[u][mt][0], ahi[u][mt][1], ahi[u][mt][2], ahi[u][mt][3]);
#pragma unroll
        for (int u = 0; u < 2; u++)
#pragma unroll
            for (int mt = 0; mt < 2; mt++)
#pragma unroll
                for (int nt = 0; nt < 4; nt++)
                    mma16816(acc[mt][nt], ahi[u][mt], bhi[u][nt]);

        __syncthreads();
        if (it + 2 < 32)
            gemm_loadslab(sb, it & 1, (it + 2) * 32, Ahi, Alo, Bhi, Blo);
    }
}

// ---------------------------------------------------------------------------
// QKV projection: epilogue writes bf16 hi/lo; Q,K,V all [b,h,s,dk] (coalesced).
// ---------------------------------------------------------------------------
__global__ __launch_bounds__(256, 2)
void qkv_mma_kernel(const float* __restrict__ bq, const float* __restrict__ bk,
                    const float* __restrict__ bv)
{
    extern __shared__ char smem[];
    const uint32_t sb = smem_u32(smem);

    const int m0   = blockIdx.x * BM;
    const int n0g  = blockIdx.y * BN;
    const int wsel = n0g >> 10;
    const int n0   = n0g & 1023;

    const float* __restrict__ bia = (wsel == 0) ? bq : ((wsel == 1) ? bk : bv);
    uint16_t* dh = (wsel == 0) ? g_Qhi : ((wsel == 1) ? g_Khi : g_Vhi);
    uint16_t* dl = (wsel == 0) ? g_Qlo : ((wsel == 1) ? g_Klo : g_Vlo);

    float acc[2][4][4];
#pragma unroll
    for (int i = 0; i < 2; i++)
#pragma unroll
        for (int j = 0; j < 4; j++)
#pragma unroll
            for (int k = 0; k < 4; k++) acc[i][j][k] = 0.f;

    gemm_mainloop(sb,
                  g_xhi + (size_t)m0 * DMODEL, g_xlo + (size_t)m0 * DMODEL,
                  g_whi + (size_t)n0g * DMODEL, g_wlo + (size_t)n0g * DMODEL,
                  acc);

    const int lane = threadIdx.x & 31;
    const int wid  = threadIdx.x >> 5;
    const int mw   = (wid & 3) * 32;
    const int nw   = (wid >> 2) * 32;

#pragma unroll
    for (int mt = 0; mt < 2; mt++) {
#pragma unroll
        for (int nt = 0; nt < 4; nt++) {
            const int n    = n0 + nw + nt * 8 + (lane & 3) * 2;
            const int head = n >> 6;
            const int dk   = n & 63;
            const float b0v = __ldg(bia + n), b1v = __ldg(bia + n + 1);
#pragma unroll
            for (int hh = 0; hh < 2; hh++) {
                const int m    = m0 + mw + mt * 16 + (lane >> 2) + hh * 8;
                const int bb   = m >> 11;
                const int srow = m & (SEQ - 1);
                const int bh   = bb * NHEADS + head;
                uint32_t hp, lp;
                split2(acc[mt][nt][hh * 2] + b0v, acc[mt][nt][hh * 2 + 1] + b1v,
                       hp, lp);
                const size_t idx = ((size_t)bh * SEQ + srow) * DK + dk;
                *(uint32_t*)(dh + idx) = hp;
                *(uint32_t*)(dl + idx) = lp;
            }
        }
    }
}

// ---------------------------------------------------------------------------
// Output projection: out = ctx·Wo^T + bo   (ctx from g_chi/g_clo)
// ---------------------------------------------------------------------------
__global__ __launch_bounds__(256, 2)
void oproj_mma_kernel(const float* __restrict__ bo, float* __restrict__ out)
{
    extern __shared__ char smem[];
    const uint32_t sb = smem_u32(smem);

    const int m0 = blockIdx.x * BM;
    const int n0 = blockIdx.y * BN;

    float acc[2][4][4];
#pragma unroll
    for (int i = 0; i < 2; i++)
#pragma unroll
        for (int j = 0; j < 4; j++)
#pragma unroll
            for (int k = 0; k < 4; k++) acc[i][j][k] = 0.f;

    gemm_mainloop(sb,
                  g_chi + (size_t)m0 * DMODEL, g_clo + (size_t)m0 * DMODEL,
                  g_whi + (size_t)(3072 + n0) * DMODEL,
                  g_wlo + (size_t)(3072 + n0) * DMODEL,
                  acc);

    const int lane = threadIdx.x & 31;
    const int wid  = threadIdx.x >> 5;
    const int mw   = (wid & 3) * 32;
    const int nw   = (wid >> 2) * 32;

#pragma unroll
    for (int mt = 0; mt < 2; mt++) {
#pragma unroll
        for (int nt = 0; nt < 4; nt++) {
            const int n = n0 + nw + nt * 8 + (lane & 3) * 2;
            const float b0v = __ldg(bo + n), b1v = __ldg(bo + n + 1);
#pragma unroll
            for (int hh = 0; hh < 2; hh++) {
                const int m = m0 + mw + mt * 16 + (lane >> 2) + hh * 8;
                float2 v = make_float2(acc[mt][nt][hh * 2] + b0v,
                                       acc[mt][nt][hh * 2 + 1] + b1v);
                *(float2*)(out + (size_t)m * DMODEL + n) = v;
            }
        }
    }
}

// ===========================================================================
// HMMA causal flash attention, 2 CTAs/SM.
// Block = (b, h, 128-query tile); 8 warps x 16 rows.
// Q lives in its own smem region (persists); Q-hi frags in registers,
// Q-lo frags reloaded from smem per tile. K,V tiles [64 keys x 64 dk hi+lo]
// double-buffered via cp.async; V B-frags via ldmatrix .trans.
// ===========================================================================
#define APITCH 272
#define KTILEB (64 * APITCH)         // 17408
#define KVBUF  (2 * KTILEB)          // 34816
#define QTILEB (128 * APITCH)        // 34816
#define ATTN_SMEM (2 * KVBUF + QTILEB)  // 104448

__device__ __forceinline__ void attn_load_tile(uint32_t dst,
    const uint16_t* __restrict__ Khi, const uint16_t* __restrict__ Klo,
    const uint16_t* __restrict__ Vhi, const uint16_t* __restrict__ Vlo, int k0)
{
    const int t = threadIdx.x;
    const int r = t >> 2, part = t & 3;
    {
        const uint16_t* hs = Khi + (size_t)(k0 + r) * DK + part * 16;
        const uint16_t* ls = Klo + (size_t)(k0 + r) * DK + part * 16;
        const uint32_t d = dst + r * APITCH + part * 32;
        cpa16(d, hs);        cpa16(d + 16, hs + 8);
        cpa16(d + 128, ls);  cpa16(d + 144, ls + 8);
    }
    {
        const uint16_t* hs = Vhi + (size_t)(k0 + r) * DK + part * 16;
        const uint16_t* ls = Vlo + (size_t)(k0 + r) * DK + part * 16;
        const uint32_t d = dst + KTILEB + r * APITCH + part * 32;
        cpa16(d, hs);        cpa16(d + 16, hs + 8);
        cpa16(d + 128, ls);  cpa16(d + 144, ls + 8);
    }
    CP_COMMIT();
}

__global__ __launch_bounds__(256, 2)
void attn_mma_kernel()
{
    extern __shared__ char smem[];
    const uint32_t sb = smem_u32(smem);
    const uint32_t sQ = sb + 2 * KVBUF;

    const int bid = blockIdx.x;
    const int qt  = bid & 15;
    const int h   = (bid >> 4) & (NHEADS - 1);
    const int b   = bid >> 8;
    const int bh  = b * NHEADS + h;
    const int q0  = qt * 128;

    const int tid = threadIdx.x, lane = tid & 31, w = tid >> 5;

    const uint16_t* Qhi = g_Qhi + (size_t)bh * SEQ * DK;
    const uint16_t* Qlo = g_Qlo + (size_t)bh * SEQ * DK;
    const uint16_t* Khi = g_Khi + (size_t)bh * SEQ * DK;
    const uint16_t* Klo = g_Klo + (size_t)bh * SEQ * DK;
    const uint16_t* Vhi = g_Vhi + (size_t)bh * SEQ * DK;
    const uint16_t* Vlo = g_Vlo + (size_t)bh * SEQ * DK;

    // ---- stage Q tile into its own smem region ----
    {
        const int r = tid >> 1, seg = tid & 1;
        const uint16_t* hs = Qhi + (size_t)(q0 + r) * DK + seg * 32;
        const uint16_t* ls = Qlo + (size_t)(q0 + r) * DK + seg * 32;
        const uint32_t d = sQ + r * APITCH + seg * 64;
#pragma unroll
        for (int c = 0; c < 4; c++) {
            cpa16(d + c * 16,       hs + c * 8);
            cpa16(d + 128 + c * 16, ls + c * 8);
        }
    }
    CP_COMMIT(); CP_WAIT(0); __syncthreads();

    const uint32_t aoffQ = sQ +
        (uint32_t)((w * 16 + (lane & 15)) * APITCH + (lane >> 4) * 16);

    uint32_t qh[4][4];
#pragma unroll
    for (int ks = 0; ks < 4; ks++)
        ldsm_x4(aoffQ + ks * 32, qh[ks][0], qh[ks][1], qh[ks][2], qh[ks][3]);

    float o[8][4];
#pragma unroll
    for (int i = 0; i < 8; i++)
#pragma unroll
        for (int j = 0; j < 4; j++) o[i][j] = 0.f;
    float m0 = -1e30f, m1 = -1e30f, l0 = 0.f, l1 = 0.f;

    const int jtmax = 2 * qt + 1;
    attn_load_tile(sb, Khi, Klo, Vhi, Vlo, 0);

    const uint32_t boffK = (uint32_t)((lane & 7) * APITCH + ((lane >> 3) & 1) * 16);
    const uint32_t boffV = (uint32_t)((lane & 15) * APITCH);

#pragma unroll 1
    for (int jt = 0; jt <= jtmax; jt++) {
        if (jt < jtmax) {
            attn_load_tile(sb + ((jt + 1) & 1) * KVBUF, Khi, Klo, Vhi, Vlo,
                           (jt + 1) * 64);
            CP_WAIT(1);
        } else {
            CP_WAIT(0);
        }
        __syncthreads();

        const uint32_t bK = sb + (jt & 1) * KVBUF;
        const uint32_t bV = bK + KTILEB;

        // ---- S = Q K^T (3-term; Q-lo frags reloaded from smem) ----
        float s[8][4];
#pragma unroll
        for (int i = 0; i < 8; i++)
#pragma unroll
            for (int j = 0; j < 4; j++) s[i][j] = 0.f;

#pragma unroll
        for (int ks = 0; ks < 4; ks++) {
            uint32_t kb[8][2], kl[8][2], ql[4];
#pragma unroll
            for (int nt = 0; nt < 8; nt++)
                ldsm_x2(bK + boffK + (uint32_t)(nt * 8 * APITCH + ks * 32),
                        kb[nt][0], kb[nt][1]);
#pragma unroll
            for (int nt = 0; nt < 8; nt++) mma16816(s[nt], qh[ks], kb[nt]);
            ldsm_x4(aoffQ + ks * 32 + 128, ql[0], ql[1], ql[2], ql[3]);
#pragma unroll
            for (int nt = 0; nt < 8; nt++) mma16816(s[nt], ql, kb[nt]);
#pragma unroll
            for (int nt = 0; nt < 8; nt++)
                ldsm_x2(bK + boffK + (uint32_t)(nt * 8 * APITCH + ks * 32 + 128),
                        kl[nt][0], kl[nt][1]);
#pragma unroll
            for (int nt = 0; nt < 8; nt++) mma16816(s[nt], qh[ks], kl[nt]);
        }

        // ---- scale + causal mask ----
        const int r0 = q0 + w * 16 + (lane >> 2);
        if (jt >= 2 * qt) {
#pragma unroll
            for (int nt = 0; nt < 8; nt++) {
                const int kg = jt * 64 + nt * 8 + (lane & 3) * 2;
#pragma unroll
                for (int e = 0; e < 4; e++) {
                    const int kge = kg + (e & 1);
                    const int qge = r0 + ((e >> 1) << 3);
                    s[nt][e] = (kge <= qge) ? s[nt][e] * 0.125f : -1e30f;
                }
            }
        } else {
#pragma unroll
            for (int nt = 0; nt < 8; nt++)
#pragma unroll
                for (int e = 0; e < 4; e++) s[nt][e] *= 0.125f;
        }

        // ---- online softmax (rows r0, r0+8) ----
        float mx0 = -1e30f, mx1 = -1e30f;
#pragma unroll
        for (int nt = 0; nt < 8; nt++) {
            mx0 = fmaxf(mx0, fmaxf(s[nt][0], s[nt][1]));
            mx1 = fmaxf(mx1, fmaxf(s[nt][2], s[nt][3]));
        }
        mx0 = fmaxf(mx0, __shfl_xor_sync(0xffffffffu, mx0, 1));
        mx0 = fmaxf(mx0, __shfl_xor_sync(0xffffffffu, mx0, 2));
        mx1 = fmaxf(mx1, __shfl_xor_sync(0xffffffffu, mx1, 1));
        mx1 = fmaxf(mx1, __shfl_xor_sync(0xffffffffu, mx1, 2));
        const float mn0 = fmaxf(m0, mx0), mn1 = fmaxf(m1, mx1);
        const float a0 = __expf(m0 - mn0), a1 = __expf(m1 - mn1);
        m0 = mn0; m1 = mn1;
        float rs0 = 0.f, rs1 = 0.f;
#pragma unroll
        for (int nt = 0; nt < 8; nt++) {
            s[nt][0] = __expf(s[nt][0] - mn0); rs0 += s[nt][0];
            s[nt][1] = __expf(s[nt][1] - mn0); rs0 += s[nt][1];
            s[nt][2] = __expf(s[nt][2] - mn1); rs1 += s[nt][2];
            s[nt][3] = __expf(s[nt][3] - mn1); rs1 += s[nt][3];
        }
        rs0 += __shfl_xor_sync(0xffffffffu, rs0, 1);
        rs0 += __shfl_xor_sync(0xffffffffu, rs0, 2);
        rs1 += __shfl_xor_sync(0xffffffffu, rs1, 1);
        rs1 += __shfl_xor_sync(0xffffffffu, rs1, 2);
        l0 = l0 * a0 + rs0;
        l1 = l1 * a1 + rs1;
#pragma unroll
        for (int nt = 0; nt < 8; nt++) {
            o[nt][0] *= a0; o[nt][1] *= a0; o[nt][2] *= a1; o[nt][3] *= a1;
        }

        // ---- O += P V  (P frags from S regs; V frags via ldsm trans) ----
#pragma unroll
        for (int ks2 = 0; ks2 < 4; ks2++) {
            uint32_t ph[4], pl[4];
            split2(s[2 * ks2][0],     s[2 * ks2][1],     ph[0], pl[0]);
            split2(s[2 * ks2][2],     s[2 * ks2][3],     ph[1], pl[1]);
            split2(s[2 * ks2 + 1][0], s[2 * ks2 + 1][1], ph[2], pl[2]);
            split2(s[2 * ks2 + 1][2], s[2 * ks2 + 1][3], ph[3], pl[3]);
            const uint32_t vrow = bV + boffV + (uint32_t)(ks2 * 16 * APITCH);
            uint32_t vh[8][2], vl[8][2];
#pragma unroll
            for (int nt = 0; nt < 8; nt++)
                ldsm_x2t(vrow + (uint32_t)(nt * 16), vh[nt][0], vh[nt][1]);
#pragma unroll
            for (int nt = 0; nt < 8; nt++) mma16816(o[nt], ph, vh[nt]);
#pragma unroll
            for (int nt = 0; nt < 8; nt++) mma16816(o[nt], pl, vh[nt]);
#pragma unroll
            for (int nt = 0; nt < 8; nt++)
                ldsm_x2t(vrow + (uint32_t)(nt * 16 + 128), vl[nt][0], vl[nt][1]);
#pragma unroll
            for (int nt = 0; nt < 8; nt++) mma16816(o[nt], ph, vl[nt]);
        }

        __syncthreads();
    }

    // ---- epilogue: normalize and write ctx hi/lo ----
    const float i0 = 1.f / l0, i1 = 1.f / l1;
    const int rq = q0 + w * 16 + (lane >> 2);
    const size_t row0 = (size_t)(b * SEQ + rq) * DMODEL + h * DK;
    const size_t row1 = row0 + (size_t)8 * DMODEL;
#pragma unroll
    for (int nt = 0; nt < 8; nt++) {
        const int c = nt * 8 + (lane & 3) * 2;
        uint32_t hp, lp;
        split2(o[nt][0] * i0, o[nt][1] * i0, hp, lp);
        *(uint32_t*)(g_chi + row0 + c) = hp;
        *(uint32_t*)(g_clo + row0 + c) = lp;
        split2(o[nt][2] * i1, o[nt][3] * i1, hp, lp);
        *(uint32_t*)(g_chi + row1 + c) = hp;
        *(uint32_t*)(g_clo + row1 + c) = lp;
    }
}

// ---------------------------------------------------------------------------
extern "C" void kernel_launch(void* const* d_in, const int* in_sizes, int n_in,
                              void* d_out, int out_size)
{
    const float* x  = (const float*)d_in[0];
    // d_in[1] = mask (causal; statically known, unused)
    const float* Wq = (const float*)d_in[2];
    const float* bq = (const float*)d_in[3];
    const float* Wk = (const float*)d_in[4];
    const float* bk = (const float*)d_in[5];
    const float* Wv = (const float*)d_in[6];
    const float* bv = (const float*)d_in[7];
    const float* Wo = (const float*)d_in[8];
    const float* bo = (const float*)d_in[9];
    float* out = (float*)d_out;

    cudaFuncSetAttribute(qkv_mma_kernel,
                         cudaFuncAttributeMaxDynamicSharedMemorySize, SMEM_G);
    cudaFuncSetAttribute(oproj_mma_kernel,
                         cudaFuncAttributeMaxDynamicSharedMemorySize, SMEM_G);
    cudaFuncSetAttribute(attn_mma_kernel,
                         cudaFuncAttributeMaxDynamicSharedMemorySize, ATTN_SMEM);

    split_x_kernel<<<(MTOT * DMODEL) / 1024, 256>>>(x);
    split_w_kernel<<<dim3((DMODEL * DMODEL) / 1024, 4), 256>>>(Wq, Wk, Wv, Wo);
    qkv_mma_kernel<<<dim3(MTOT / BM, 3 * DMODEL / BN), 256, SMEM_G>>>(bq, bk, bv);
    attn_mma_kernel<<<BATCH * NHEADS * (SEQ / 128), 256, ATTN_SMEM>>>();
    oproj_mma_kernel<<<dim3(MTOT / BM, DMODEL / BN), 256, SMEM_G>>>(bo, out);
}